// round 6
// baseline (speedup 1.0000x reference)
#include <cuda_runtime.h>
#include <math.h>
#include <stdint.h>

#define BB   4
#define SEQ  1024
#define EMB  1024
#define NH   16
#define HD   64
#define DFF  4096
#define MROWS (BB*SEQ)   // 4096

// ---------------- scratch (static device globals; no allocation) ----------------
__device__ float g_nx [MROWS*EMB];
__device__ float g_q  [MROWS*EMB];
__device__ float g_k  [MROWS*EMB];
__device__ float g_v  [MROWS*EMB];
__device__ float g_vt [BB*NH*HD*SEQ];            // V transposed per head: [bh][d][seq]
__device__ float g_o  [MROWS*EMB];
__device__ float g_x1 [MROWS*EMB];
__device__ float g_nx2[MROWS*EMB];
__device__ float g_h  [MROWS*DFF];
__device__ float g_s  [(size_t)BB*NH*SEQ*SEQ];   // 256 MB attention scores

// ---------------- helpers ----------------
__device__ __forceinline__ uint32_t f2tf32(float f) {
    uint32_t u;
    asm("cvt.rna.tf32.f32 %0, %1;" : "=r"(u) : "f"(f));
    return u;
}

__device__ __forceinline__ void mma8(float c[4], const uint4& a, uint32_t b0, uint32_t b1) {
    asm volatile(
        "mma.sync.aligned.m16n8k8.row.col.f32.tf32.tf32.f32 "
        "{%0,%1,%2,%3},{%4,%5,%6,%7},{%8,%9},{%0,%1,%2,%3};"
        : "+f"(c[0]), "+f"(c[1]), "+f"(c[2]), "+f"(c[3])
        : "r"(a.x), "r"(a.y), "r"(a.z), "r"(a.w), "r"(b0), "r"(b1));
}

__device__ __forceinline__ float gelu_f(float x) {
    const float c = 0.7978845608028654f;  // sqrt(2/pi)
    float t = tanhf(c * (x + 0.044715f * x * x * x));
    return 0.5f * x * (1.0f + t);
}

// Staging layout constants (conflict-free):
// A: Aw[kstep*1028 + m16*128 + (m7*4+c)*4 + (rhalf + 2*k4)]   (4112 words)
// B (16 n8 blocks): Bw[kpair*2120 + n8*132 + (n7*4+c)*4 + (2*(kstep&1)+k4)]  (4240 words)
// B ( 8 n8 blocks): kpair stride 1064  (2128 words)
#define A_WORDS 4112
#define B_WORDS_128 4240
#define B_WORDS_64  2128
#define BUF_WORDS_128 (A_WORDS + B_WORDS_128)   // 8352
#define BUF_WORDS_64  (A_WORDS + B_WORDS_64)    // 6240
#define GEMM_SMEM_BYTES (2 * BUF_WORDS_128 * 4) // 66816
#define PV_SMEM_BYTES   (2 * BUF_WORDS_64 * 4)  // 49920

// ---------------- LayerNorm (one block per row of 1024) ----------------
__global__ __launch_bounds__(256)
void layernorm_k(const float* __restrict__ x, const float* __restrict__ g,
                 const float* __restrict__ b, float* __restrict__ out)
{
    __shared__ float red[8];
    const int row = blockIdx.x;
    const int tid = threadIdx.x;
    const float* xr = x + (size_t)row * EMB;

    float4 f = reinterpret_cast<const float4*>(xr)[tid];

    float s = f.x + f.y + f.z + f.w;
    #pragma unroll
    for (int o = 16; o > 0; o >>= 1) s += __shfl_xor_sync(0xffffffffu, s, o);
    if ((tid & 31) == 0) red[tid >> 5] = s;
    __syncthreads();
    float mean = 0.f;
    #pragma unroll
    for (int i = 0; i < 8; i++) mean += red[i];
    mean *= (1.0f / (float)EMB);
    __syncthreads();

    float dx0 = f.x - mean, dx1 = f.y - mean, dx2 = f.z - mean, dx3 = f.w - mean;
    float ss = dx0*dx0 + dx1*dx1 + dx2*dx2 + dx3*dx3;
    #pragma unroll
    for (int o = 16; o > 0; o >>= 1) ss += __shfl_xor_sync(0xffffffffu, ss, o);
    if ((tid & 31) == 0) red[tid >> 5] = ss;
    __syncthreads();
    float var = 0.f;
    #pragma unroll
    for (int i = 0; i < 8; i++) var += red[i];
    var *= (1.0f / (float)(EMB - 1));
    const float rs = 1.0f / (sqrtf(var) + 1e-8f);

    const float4 gg = reinterpret_cast<const float4*>(g)[tid];
    const float4 bb = reinterpret_cast<const float4*>(b)[tid];
    float4 r;
    r.x = gg.x * dx0 * rs + bb.x;
    r.y = gg.y * dx1 * rs + bb.y;
    r.z = gg.z * dx2 * rs + bb.z;
    r.w = gg.w * dx3 * rs + bb.w;
    reinterpret_cast<float4*>(out + (size_t)row * EMB)[tid] = r;
}

// ================= tf32 mma.sync GEMM, conflict-free staging, double-buffered =================
// C = epi(A @ W^T + bias) [+ res]; A[M,K], W[N,K] row-major. BM=BN=128, BK=32.
// 8 warps (2M x 4N), warp tile 64x32. One __syncthreads per ktile.
template <int EPI>   // 0 = none, 1 = gelu
__global__ __launch_bounds__(256)
void gemm_tc(const float* __restrict__ A, const float* __restrict__ W,
             const float* __restrict__ bias, const float* __restrict__ res,
             float* __restrict__ C, int M, int N, int K)
{
    extern __shared__ uint32_t dyn[];

    const int tid = threadIdx.x;
    const int lane = tid & 31;
    const int wid = tid >> 5;
    const int warpM = wid >> 2, warpN = wid & 3;
    const int bm = blockIdx.y * 128;
    const int bn = blockIdx.x * 128;

    const int chunk = lane & 7;
    const int kstep = chunk >> 1;
    const int k4 = chunk & 1;
    const int kpair = kstep >> 1;
    const int rbase = (((lane >> 3) & 1)) | ((wid & 3) << 1) | (((lane >> 4) & 1) << 3) | ((wid >> 2) << 4);

    // per-thread staging indices (loop invariant)
    int aIdx[4], bIdx[4];
    #pragma unroll
    for (int lp = 0; lp < 4; lp++) {
        int r = rbase + (lp << 5);
        aIdx[lp] = kstep * 1028 + (r >> 4) * 128 + (r & 7) * 16 + ((r >> 3) & 1) + 2 * k4;
        bIdx[lp] = kpair * 2120 + (r >> 3) * 132 + (r & 7) * 16 + 2 * (kstep & 1) + k4;
    }

    float acc[4][4][4];
    #pragma unroll
    for (int i = 0; i < 4; i++)
        #pragma unroll
        for (int j = 0; j < 4; j++)
            #pragma unroll
            for (int r = 0; r < 4; r++) acc[i][j][r] = 0.f;

    const int nk = K >> 5;
    float4 ra[4], rb[4];

    // prologue: load + stage tile 0 into buf0
    #pragma unroll
    for (int lp = 0; lp < 4; lp++) {
        int r = rbase + (lp << 5);
        ra[lp] = *reinterpret_cast<const float4*>(A + (size_t)(bm + r) * K + chunk * 4);
        rb[lp] = *reinterpret_cast<const float4*>(W + (size_t)(bn + r) * K + chunk * 4);
    }
    {
        uint32_t* Aw = dyn;
        uint32_t* Bw = dyn + A_WORDS;
        #pragma unroll
        for (int lp = 0; lp < 4; lp++) {
            float av[4] = {ra[lp].x, ra[lp].y, ra[lp].z, ra[lp].w};
            float bv[4] = {rb[lp].x, rb[lp].y, rb[lp].z, rb[lp].w};
            #pragma unroll
            for (int c = 0; c < 4; c++) {
                Aw[aIdx[lp] + 4 * c] = f2tf32(av[c]);
                Bw[bIdx[lp] + 4 * c] = f2tf32(bv[c]);
            }
        }
    }
    __syncthreads();

    for (int kt = 0; kt < nk; kt++) {
        const int cur = kt & 1;
        uint32_t* Aw = dyn + cur * BUF_WORDS_128;
        uint32_t* Bw = Aw + A_WORDS;
        uint32_t* An = dyn + (cur ^ 1) * BUF_WORDS_128;
        uint32_t* Bn = An + A_WORDS;

        // issue global loads for next tile (latency hidden by MMAs below)
        if (kt + 1 < nk) {
            int k0 = (kt + 1) << 5;
            #pragma unroll
            for (int lp = 0; lp < 4; lp++) {
                int r = rbase + (lp << 5);
                ra[lp] = *reinterpret_cast<const float4*>(A + (size_t)(bm + r) * K + k0 + chunk * 4);
                rb[lp] = *reinterpret_cast<const float4*>(W + (size_t)(bn + r) * K + k0 + chunk * 4);
            }
        }

        // compute current tile
        uint4 bf[2][4];
        #pragma unroll
        for (int kp = 0; kp < 2; kp++)
            #pragma unroll
            for (int j = 0; j < 4; j++)
                bf[kp][j] = *reinterpret_cast<const uint4*>(&Bw[kp * 2120 + (warpN * 4 + j) * 132 + lane * 4]);

        #pragma unroll
        for (int ks = 0; ks < 4; ks++) {
            uint4 af[4];
            #pragma unroll
            for (int i = 0; i < 4; i++)
                af[i] = *reinterpret_cast<const uint4*>(&Aw[ks * 1028 + (warpM * 4 + i) * 128 + lane * 4]);
            const int kp = ks >> 1, odd = ks & 1;
            #pragma unroll
            for (int i = 0; i < 4; i++)
                #pragma unroll
                for (int j = 0; j < 4; j++) {
                    uint32_t b0 = odd ? bf[kp][j].z : bf[kp][j].x;
                    uint32_t b1 = odd ? bf[kp][j].w : bf[kp][j].y;
                    mma8(acc[i][j], af[i], b0, b1);
                }
        }

        // stage next tile into the other buffer
        if (kt + 1 < nk) {
            #pragma unroll
            for (int lp = 0; lp < 4; lp++) {
                float av[4] = {ra[lp].x, ra[lp].y, ra[lp].z, ra[lp].w};
                float bv[4] = {rb[lp].x, rb[lp].y, rb[lp].z, rb[lp].w};
                #pragma unroll
                for (int c = 0; c < 4; c++) {
                    An[aIdx[lp] + 4 * c] = f2tf32(av[c]);
                    Bn[bIdx[lp] + 4 * c] = f2tf32(bv[c]);
                }
            }
        }
        __syncthreads();
    }

    const int gid = lane >> 2, tig = lane & 3;
    #pragma unroll
    for (int i = 0; i < 4; i++) {
        int row0 = bm + warpM * 64 + i * 16 + gid;
        #pragma unroll
        for (int j = 0; j < 4; j++) {
            int col = bn + warpN * 32 + j * 8 + tig * 2;
            float b0 = bias[col], b1 = bias[col + 1];
            float v0 = acc[i][j][0] + b0;
            float v1 = acc[i][j][1] + b1;
            float v2 = acc[i][j][2] + b0;
            float v3 = acc[i][j][3] + b1;
            if (EPI == 1) { v0 = gelu_f(v0); v1 = gelu_f(v1); v2 = gelu_f(v2); v3 = gelu_f(v3); }
            if (res) {
                v0 += res[(size_t)row0 * N + col];
                v1 += res[(size_t)row0 * N + col + 1];
                v2 += res[(size_t)(row0 + 8) * N + col];
                v3 += res[(size_t)(row0 + 8) * N + col + 1];
            }
            *reinterpret_cast<float2*>(C + (size_t)row0 * N + col)       = make_float2(v0, v1);
            *reinterpret_cast<float2*>(C + (size_t)(row0 + 8) * N + col) = make_float2(v2, v3);
        }
    }
}

// ================= tf32 scores: S = mask(Q K^T / 8), 128x128 tile, K=64, double-buffered =================
__global__ __launch_bounds__(256)
void attn_scores_tc(const float* __restrict__ q, const float* __restrict__ kk,
                    const int* __restrict__ mask, float* __restrict__ s)
{
    extern __shared__ uint32_t dyn[];

    const int tid = threadIdx.x;
    const int lane = tid & 31;
    const int wid = tid >> 5;
    const int warpM = wid >> 2, warpN = wid & 3;
    const int bh = blockIdx.z;
    const int b = bh >> 4, h = bh & 15;
    const int bm = blockIdx.y * 128;
    const int bn = blockIdx.x * 128;

    const int chunk = lane & 7;
    const int kstep = chunk >> 1;
    const int k4 = chunk & 1;
    const int kpair = kstep >> 1;
    const int rbase = (((lane >> 3) & 1)) | ((wid & 3) << 1) | (((lane >> 4) & 1) << 3) | ((wid >> 2) << 4);

    int aIdx[4], bIdx[4];
    #pragma unroll
    for (int lp = 0; lp < 4; lp++) {
        int r = rbase + (lp << 5);
        aIdx[lp] = kstep * 1028 + (r >> 4) * 128 + (r & 7) * 16 + ((r >> 3) & 1) + 2 * k4;
        bIdx[lp] = kpair * 2120 + (r >> 3) * 132 + (r & 7) * 16 + 2 * (kstep & 1) + k4;
    }

    const float* aptr = q  + (size_t)(b * SEQ + bm) * EMB + h * HD;
    const float* bptr = kk + (size_t)(b * SEQ + bn) * EMB + h * HD;

    float acc[4][4][4];
    #pragma unroll
    for (int i = 0; i < 4; i++)
        #pragma unroll
        for (int j = 0; j < 4; j++)
            #pragma unroll
            for (int r = 0; r < 4; r++) acc[i][j][r] = 0.f;

    float4 ra[4], rb[4];
    #pragma unroll
    for (int lp = 0; lp < 4; lp++) {
        int r = rbase + (lp << 5);
        ra[lp] = *reinterpret_cast<const float4*>(aptr + (size_t)r * EMB + chunk * 4);
        rb[lp] = *reinterpret_cast<const float4*>(bptr + (size_t)r * EMB + chunk * 4);
    }
    {
        uint32_t* Aw = dyn;
        uint32_t* Bw = dyn + A_WORDS;
        #pragma unroll
        for (int lp = 0; lp < 4; lp++) {
            float av[4] = {ra[lp].x, ra[lp].y, ra[lp].z, ra[lp].w};
            float bv[4] = {rb[lp].x, rb[lp].y, rb[lp].z, rb[lp].w};
            #pragma unroll
            for (int c = 0; c < 4; c++) {
                Aw[aIdx[lp] + 4 * c] = f2tf32(av[c]);
                Bw[bIdx[lp] + 4 * c] = f2tf32(bv[c]);
            }
        }
    }
    __syncthreads();

    #pragma unroll
    for (int kt = 0; kt < 2; kt++) {
        const int cur = kt & 1;
        uint32_t* Aw = dyn + cur * BUF_WORDS_128;
        uint32_t* Bw = Aw + A_WORDS;
        uint32_t* An = dyn + (cur ^ 1) * BUF_WORDS_128;
        uint32_t* Bn = An + A_WORDS;

        if (kt == 0) {
            #pragma unroll
            for (int lp = 0; lp < 4; lp++) {
                int r = rbase + (lp << 5);
                ra[lp] = *reinterpret_cast<const float4*>(aptr + (size_t)r * EMB + 32 + chunk * 4);
                rb[lp] = *reinterpret_cast<const float4*>(bptr + (size_t)r * EMB + 32 + chunk * 4);
            }
        }

        uint4 bf[2][4];
        #pragma unroll
        for (int kp = 0; kp < 2; kp++)
            #pragma unroll
            for (int j = 0; j < 4; j++)
                bf[kp][j] = *reinterpret_cast<const uint4*>(&Bw[kp * 2120 + (warpN * 4 + j) * 132 + lane * 4]);

        #pragma unroll
        for (int ks = 0; ks < 4; ks++) {
            uint4 af[4];
            #pragma unroll
            for (int i = 0; i < 4; i++)
                af[i] = *reinterpret_cast<const uint4*>(&Aw[ks * 1028 + (warpM * 4 + i) * 128 + lane * 4]);
            const int kp = ks >> 1, odd = ks & 1;
            #pragma unroll
            for (int i = 0; i < 4; i++)
                #pragma unroll
                for (int j = 0; j < 4; j++) {
                    uint32_t b0 = odd ? bf[kp][j].z : bf[kp][j].x;
                    uint32_t b1 = odd ? bf[kp][j].w : bf[kp][j].y;
                    mma8(acc[i][j], af[i], b0, b1);
                }
        }

        if (kt == 0) {
            #pragma unroll
            for (int lp = 0; lp < 4; lp++) {
                float av[4] = {ra[lp].x, ra[lp].y, ra[lp].z, ra[lp].w};
                float bv[4] = {rb[lp].x, rb[lp].y, rb[lp].z, rb[lp].w};
                #pragma unroll
                for (int c = 0; c < 4; c++) {
                    An[aIdx[lp] + 4 * c] = f2tf32(av[c]);
                    Bn[bIdx[lp] + 4 * c] = f2tf32(bv[c]);
                }
            }
        }
        __syncthreads();
    }

    const int gid = lane >> 2, tig = lane & 3;
    #pragma unroll
    for (int i = 0; i < 4; i++) {
        int row0 = bm + warpM * 64 + i * 16 + gid;
        #pragma unroll
        for (int j = 0; j < 4; j++) {
            int col = bn + warpN * 32 + j * 8 + tig * 2;
            int2 m0 = *reinterpret_cast<const int2*>(&mask[((size_t)b * SEQ + row0) * SEQ + col]);
            int2 m1 = *reinterpret_cast<const int2*>(&mask[((size_t)b * SEQ + row0 + 8) * SEQ + col]);
            float2 o0, o1;
            o0.x = m0.x ? acc[i][j][0] * 0.125f : -0.01f;
            o0.y = m0.y ? acc[i][j][1] * 0.125f : -0.01f;
            o1.x = m1.x ? acc[i][j][2] * 0.125f : -0.01f;
            o1.y = m1.y ? acc[i][j][3] * 0.125f : -0.01f;
            *reinterpret_cast<float2*>(s + ((size_t)bh * SEQ + row0) * SEQ + col)     = o0;
            *reinterpret_cast<float2*>(s + ((size_t)bh * SEQ + row0 + 8) * SEQ + col) = o1;
        }
    }
}

// ================= V transpose per head: vt[bh][d][s] = v[b][s][h*64+d] =================
__global__ __launch_bounds__(256)
void transpose_v_k(const float* __restrict__ v, float* __restrict__ vt)
{
    __shared__ float t[32][33];
    const int bh = blockIdx.z;
    const int b = bh >> 4, h = bh & 15;
    const int s0 = blockIdx.x * 32;
    const int d0 = blockIdx.y * 32;
    const int x = threadIdx.x & 31;
    const int y0 = threadIdx.x >> 5;   // 0..7

    #pragma unroll
    for (int j = 0; j < 4; j++) {
        int sr = y0 + j * 8;
        t[sr][x] = v[((size_t)(b * SEQ + s0 + sr)) * EMB + h * HD + d0 + x];
    }
    __syncthreads();
    #pragma unroll
    for (int j = 0; j < 4; j++) {
        int dr = y0 + j * 8;
        vt[((size_t)bh * HD + d0 + dr) * SEQ + s0 + x] = t[x][dr];
    }
}

// ================= tf32 PV: O = P @ V, 128(q) x 64(d), K=SEQ, double-buffered =================
__global__ __launch_bounds__(256)
void attn_pv_tc(const float* __restrict__ s, const float* __restrict__ vt,
                float* __restrict__ o)
{
    extern __shared__ uint32_t dyn[];

    const int tid = threadIdx.x;
    const int lane = tid & 31;
    const int wid = tid >> 5;
    const int warpM = wid >> 2, warpN = wid & 3;   // warp tile 64 x 16
    const int bh = blockIdx.y;
    const int b = bh >> 4, h = bh & 15;
    const int bm = blockIdx.x * 128;

    const int chunk = lane & 7;
    const int kstep = chunk >> 1;
    const int k4 = chunk & 1;
    const int kpair = kstep >> 1;
    const int rbase = (((lane >> 3) & 1)) | ((wid & 3) << 1) | (((lane >> 4) & 1) << 3) | ((wid >> 2) << 4);

    int aIdx[4], bIdx[2];
    #pragma unroll
    for (int lp = 0; lp < 4; lp++) {
        int r = rbase + (lp << 5);
        aIdx[lp] = kstep * 1028 + (r >> 4) * 128 + (r & 7) * 16 + ((r >> 3) & 1) + 2 * k4;
    }
    #pragma unroll
    for (int lp = 0; lp < 2; lp++) {
        int r = rbase + (lp << 5);
        bIdx[lp] = kpair * 1064 + (r >> 3) * 132 + (r & 7) * 16 + 2 * (kstep & 1) + k4;
    }

    const float* aptr = s + (size_t)bh * SEQ * SEQ + (size_t)bm * SEQ;
    const float* bptr = vt + (size_t)bh * HD * SEQ;

    float acc[4][2][4];
    #pragma unroll
    for (int i = 0; i < 4; i++)
        #pragma unroll
        for (int j = 0; j < 2; j++)
            #pragma unroll
            for (int r = 0; r < 4; r++) acc[i][j][r] = 0.f;

    float4 ra[4], rb[2];
    #pragma unroll
    for (int lp = 0; lp < 4; lp++) {
        int r = rbase + (lp << 5);
        ra[lp] = *reinterpret_cast<const float4*>(aptr + (size_t)r * SEQ + chunk * 4);
    }
    #pragma unroll
    for (int lp = 0; lp < 2; lp++) {
        int r = rbase + (lp << 5);
        rb[lp] = *reinterpret_cast<const float4*>(bptr + (size_t)r * SEQ + chunk * 4);
    }
    {
        uint32_t* Aw = dyn;
        uint32_t* Bw = dyn + A_WORDS;
        #pragma unroll
        for (int lp = 0; lp < 4; lp++) {
            float av[4] = {ra[lp].x, ra[lp].y, ra[lp].z, ra[lp].w};
            #pragma unroll
            for (int c = 0; c < 4; c++) Aw[aIdx[lp] + 4 * c] = f2tf32(av[c]);
        }
        #pragma unroll
        for (int lp = 0; lp < 2; lp++) {
            float bv[4] = {rb[lp].x, rb[lp].y, rb[lp].z, rb[lp].w};
            #pragma unroll
            for (int c = 0; c < 4; c++) Bw[bIdx[lp] + 4 * c] = f2tf32(bv[c]);
        }
    }
    __syncthreads();

    for (int kt = 0; kt < SEQ / 32; kt++) {
        const int cur = kt & 1;
        uint32_t* Aw = dyn + cur * BUF_WORDS_64;
        uint32_t* Bw = Aw + A_WORDS;
        uint32_t* An = dyn + (cur ^ 1) * BUF_WORDS_64;
        uint32_t* Bn = An + A_WORDS;

        if (kt + 1 < SEQ / 32) {
            int k0 = (kt + 1) << 5;
            #pragma unroll
            for (int lp = 0; lp < 4; lp++) {
                int r = rbase + (lp << 5);
                ra[lp] = *reinterpret_cast<const float4*>(aptr + (size_t)r * SEQ + k0 + chunk * 4);
            }
            #pragma unroll
            for (int lp = 0; lp < 2; lp++) {
                int r = rbase + (lp << 5);
                rb[lp] = *reinterpret_cast<const float4*>(bptr + (size_t)r * SEQ + k0 + chunk * 4);
            }
        }

        uint4 bf[2][2];
        #pragma unroll
        for (int kp = 0; kp < 2; kp++)
            #pragma unroll
            for (int j = 0; j < 2; j++)
                bf[kp][j] = *reinterpret_cast<const uint4*>(&Bw[kp * 1064 + (warpN * 2 + j) * 132 + lane * 4]);

        #pragma unroll
        for (int ks = 0; ks < 4; ks++) {
            uint4 af[4];
            #pragma unroll
            for (int i = 0; i < 4; i++)
                af[i] = *reinterpret_cast<const uint4*>(&Aw[ks * 1028 + (warpM * 4 + i) * 128 + lane * 4]);
            const int kp = ks >> 1, odd = ks & 1;
            #pragma unroll
            for (int i = 0; i < 4; i++)
                #pragma unroll
                for (int j = 0; j < 2; j++) {
                    uint32_t b0 = odd ? bf[kp][j].z : bf[kp][j].x;
                    uint32_t b1 = odd ? bf[kp][j].w : bf[kp][j].y;
                    mma8(acc[i][j], af[i], b0, b1);
                }
        }

        if (kt + 1 < SEQ / 32) {
            #pragma unroll
            for (int lp = 0; lp < 4; lp++) {
                float av[4] = {ra[lp].x, ra[lp].y, ra[lp].z, ra[lp].w};
                #pragma unroll
                for (int c = 0; c < 4; c++) An[aIdx[lp] + 4 * c] = f2tf32(av[c]);
            }
            #pragma unroll
            for (int lp = 0; lp < 2; lp++) {
                float bv[4] = {rb[lp].x, rb[lp].y, rb[lp].z, rb[lp].w};
                #pragma unroll
                for (int c = 0; c < 4; c++) Bn[bIdx[lp] + 4 * c] = f2tf32(bv[c]);
            }
        }
        __syncthreads();
    }

    const int gid = lane >> 2, tig = lane & 3;
    #pragma unroll
    for (int i = 0; i < 4; i++) {
        int row0 = bm + warpM * 64 + i * 16 + gid;
        #pragma unroll
        for (int j = 0; j < 2; j++) {
            int col = warpN * 16 + j * 8 + tig * 2;
            *reinterpret_cast<float2*>(o + ((size_t)(b * SEQ + row0)) * EMB + h * HD + col) =
                make_float2(acc[i][j][0], acc[i][j][1]);
            *reinterpret_cast<float2*>(o + ((size_t)(b * SEQ + row0 + 8)) * EMB + h * HD + col) =
                make_float2(acc[i][j][2], acc[i][j][3]);
        }
    }
}

// ---------------- Softmax over rows of 1024, in place ----------------
__global__ __launch_bounds__(256)
void softmax_k(float* __restrict__ s)
{
    __shared__ float red[8];
    const size_t row = blockIdx.x;
    const int tid = threadIdx.x;
    float* p = s + row * (size_t)SEQ;

    float4 f = reinterpret_cast<float4*>(p)[tid];
    float m = fmaxf(fmaxf(f.x, f.y), fmaxf(f.z, f.w));
    #pragma unroll
    for (int o = 16; o > 0; o >>= 1) m = fmaxf(m, __shfl_xor_sync(0xffffffffu, m, o));
    if ((tid & 31) == 0) red[tid >> 5] = m;
    __syncthreads();
    float mx = red[0];
    #pragma unroll
    for (int i = 1; i < 8; i++) mx = fmaxf(mx, red[i]);
    __syncthreads();

    f.x = expf(f.x - mx); f.y = expf(f.y - mx);
    f.z = expf(f.z - mx); f.w = expf(f.w - mx);
    float sm = f.x + f.y + f.z + f.w;
    #pragma unroll
    for (int o = 16; o > 0; o >>= 1) sm += __shfl_xor_sync(0xffffffffu, sm, o);
    if ((tid & 31) == 0) red[tid >> 5] = sm;
    __syncthreads();
    float tot = 0.f;
    #pragma unroll
    for (int i = 0; i < 8; i++) tot += red[i];
    float inv = 1.0f / tot;

    f.x *= inv; f.y *= inv; f.z *= inv; f.w *= inv;
    reinterpret_cast<float4*>(p)[tid] = f;
}

// ---------------- launch ----------------
extern "C" void kernel_launch(void* const* d_in, const int* in_sizes, int n_in,
                              void* d_out, int out_size)
{
    const float* x   = (const float*)d_in[0];
    const int*   mask= (const int*)  d_in[1];
    const float* Wq  = (const float*)d_in[2];
    const float* bq  = (const float*)d_in[3];
    const float* Wk  = (const float*)d_in[4];
    const float* bk  = (const float*)d_in[5];
    const float* Wv  = (const float*)d_in[6];
    const float* bv  = (const float*)d_in[7];
    const float* Wo  = (const float*)d_in[8];
    const float* bo  = (const float*)d_in[9];
    const float* W1  = (const float*)d_in[10];
    const float* b1  = (const float*)d_in[11];
    const float* W2  = (const float*)d_in[12];
    const float* b2  = (const float*)d_in[13];
    const float* g1  = (const float*)d_in[14];
    const float* be1 = (const float*)d_in[15];
    const float* g2  = (const float*)d_in[16];
    const float* be2 = (const float*)d_in[17];
    float* out = (float*)d_out;

    float *nx, *q, *k, *v, *vt, *o, *x1, *nx2, *hbuf, *sbuf;
    cudaGetSymbolAddress((void**)&nx,   g_nx);
    cudaGetSymbolAddress((void**)&q,    g_q);
    cudaGetSymbolAddress((void**)&k,    g_k);
    cudaGetSymbolAddress((void**)&v,    g_v);
    cudaGetSymbolAddress((void**)&vt,   g_vt);
    cudaGetSymbolAddress((void**)&o,    g_o);
    cudaGetSymbolAddress((void**)&x1,   g_x1);
    cudaGetSymbolAddress((void**)&nx2,  g_nx2);
    cudaGetSymbolAddress((void**)&hbuf, g_h);
    cudaGetSymbolAddress((void**)&sbuf, g_s);

    cudaFuncSetAttribute(gemm_tc<0>, cudaFuncAttributeMaxDynamicSharedMemorySize, GEMM_SMEM_BYTES);
    cudaFuncSetAttribute(gemm_tc<1>, cudaFuncAttributeMaxDynamicSharedMemorySize, GEMM_SMEM_BYTES);
    cudaFuncSetAttribute(attn_scores_tc, cudaFuncAttributeMaxDynamicSharedMemorySize, GEMM_SMEM_BYTES);
    cudaFuncSetAttribute(attn_pv_tc, cudaFuncAttributeMaxDynamicSharedMemorySize, PV_SMEM_BYTES);

    const dim3 gEE(EMB / 128, MROWS / 128);
    const dim3 gFF(DFF / 128, MROWS / 128);

    layernorm_k<<<MROWS, 256>>>(x, g1, be1, nx);
    gemm_tc<0><<<gEE, 256, GEMM_SMEM_BYTES>>>(nx, Wq, bq, nullptr, q, MROWS, EMB, EMB);
    gemm_tc<0><<<gEE, 256, GEMM_SMEM_BYTES>>>(nx, Wk, bk, nullptr, k, MROWS, EMB, EMB);
    gemm_tc<0><<<gEE, 256, GEMM_SMEM_BYTES>>>(nx, Wv, bv, nullptr, v, MROWS, EMB, EMB);

    transpose_v_k<<<dim3(SEQ / 32, HD / 32, BB * NH), 256>>>(v, vt);
    attn_scores_tc<<<dim3(SEQ / 128, SEQ / 128, BB * NH), 256, GEMM_SMEM_BYTES>>>(q, k, mask, sbuf);
    softmax_k<<<BB * NH * SEQ, 256>>>(sbuf);
    attn_pv_tc<<<dim3(SEQ / 128, BB * NH), 256, PV_SMEM_BYTES>>>(sbuf, vt, o);

    gemm_tc<0><<<gEE, 256, GEMM_SMEM_BYTES>>>(o, Wo, bo, x, x1, MROWS, EMB, EMB);
    layernorm_k<<<MROWS, 256>>>(x1, g2, be2, nx2);
    gemm_tc<1><<<gFF, 256, GEMM_SMEM_BYTES>>>(nx2, W1, b1, nullptr, hbuf, MROWS, DFF, EMB);
    gemm_tc<0><<<gEE, 256, GEMM_SMEM_BYTES>>>(hbuf, W2, b2, x1, out, MROWS, EMB, DFF);
}

// round 10
// speedup vs baseline: 1.1460x; 1.1460x over previous
#include <cuda_runtime.h>
#include <math.h>
#include <stdint.h>

#define BB   4
#define SEQ  1024
#define EMB  1024
#define NH   16
#define HD   64
#define DFF  4096
#define MROWS (BB*SEQ)   // 4096

// ---------------- scratch (static device globals; no allocation) ----------------
__device__ float g_nx [MROWS*EMB];
__device__ float g_q  [MROWS*EMB];
__device__ float g_k  [MROWS*EMB];
__device__ float g_v  [MROWS*EMB];
__device__ float g_vt [BB*NH*HD*SEQ];   // V transposed per head: [bh][d][seq]
__device__ float g_o  [MROWS*EMB];
__device__ float g_x1 [MROWS*EMB];
__device__ float g_nx2[MROWS*EMB];
__device__ float g_h  [MROWS*DFF];

// ---------------- helpers ----------------
__device__ __forceinline__ uint32_t f2tf32(float f) {
    uint32_t u;
    asm("cvt.rna.tf32.f32 %0, %1;" : "=r"(u) : "f"(f));
    return u;
}

__device__ __forceinline__ void mma8(float c[4], const uint4& a, uint32_t b0, uint32_t b1) {
    asm volatile(
        "mma.sync.aligned.m16n8k8.row.col.f32.tf32.tf32.f32 "
        "{%0,%1,%2,%3},{%4,%5,%6,%7},{%8,%9},{%0,%1,%2,%3};"
        : "+f"(c[0]), "+f"(c[1]), "+f"(c[2]), "+f"(c[3])
        : "r"(a.x), "r"(a.y), "r"(a.z), "r"(a.w), "r"(b0), "r"(b1));
}

__device__ __forceinline__ float gelu_f(float x) {
    const float c = 0.7978845608028654f;  // sqrt(2/pi)
    float t = tanhf(c * (x + 0.044715f * x * x * x));
    return 0.5f * x * (1.0f + t);
}

// Frag-order staging layouts (conflict-free; bank-verified in R4):
// A (128 rows, 32 k): word = kstep*1028 + m16*128 + (m&7)*16 + ((m>>3)&1) + 2*k4 + 4*c
// B128 (128 rows, 32 k): word = kpair*2120 + n8*132 + (n&7)*16 + 2*(kstep&1) + k4 + 4*c
// B64  ( 64 rows, 32 k): kpair stride 1064
#define A_WORDS 4112
#define B_WORDS_128 4240
#define B_WORDS_64  2128

// ---------------- LayerNorm (one block per row of 1024) ----------------
__global__ __launch_bounds__(256)
void layernorm_k(const float* __restrict__ x, const float* __restrict__ g,
                 const float* __restrict__ b, float* __restrict__ out)
{
    __shared__ float red[8];
    const int row = blockIdx.x;
    const int tid = threadIdx.x;
    const float* xr = x + (size_t)row * EMB;

    float4 f = reinterpret_cast<const float4*>(xr)[tid];

    float s = f.x + f.y + f.z + f.w;
    #pragma unroll
    for (int o = 16; o > 0; o >>= 1) s += __shfl_xor_sync(0xffffffffu, s, o);
    if ((tid & 31) == 0) red[tid >> 5] = s;
    __syncthreads();
    float mean = 0.f;
    #pragma unroll
    for (int i = 0; i < 8; i++) mean += red[i];
    mean *= (1.0f / (float)EMB);
    __syncthreads();

    float dx0 = f.x - mean, dx1 = f.y - mean, dx2 = f.z - mean, dx3 = f.w - mean;
    float ss = dx0*dx0 + dx1*dx1 + dx2*dx2 + dx3*dx3;
    #pragma unroll
    for (int o = 16; o > 0; o >>= 1) ss += __shfl_xor_sync(0xffffffffu, ss, o);
    if ((tid & 31) == 0) red[tid >> 5] = ss;
    __syncthreads();
    float var = 0.f;
    #pragma unroll
    for (int i = 0; i < 8; i++) var += red[i];
    var *= (1.0f / (float)(EMB - 1));
    const float rs = 1.0f / (sqrtf(var) + 1e-8f);

    const float4 gg = reinterpret_cast<const float4*>(g)[tid];
    const float4 bb = reinterpret_cast<const float4*>(b)[tid];
    float4 r;
    r.x = gg.x * dx0 * rs + bb.x;
    r.y = gg.y * dx1 * rs + bb.y;
    r.z = gg.z * dx2 * rs + bb.z;
    r.w = gg.w * dx3 * rs + bb.w;
    reinterpret_cast<float4*>(out + (size_t)row * EMB)[tid] = r;
}

// ================= tf32 mma.sync GEMM body (R4 single-buffer version) =================
template <int EPI>   // 0 = none, 1 = gelu
__device__ __forceinline__
void gemm_body(const float* __restrict__ A, const float* __restrict__ W,
               const float* __restrict__ bias, const float* __restrict__ res,
               float* __restrict__ C, int M, int N, int K)
{
    __shared__ uint32_t Aw[A_WORDS];
    __shared__ uint32_t Bw[B_WORDS_128];

    const int tid = threadIdx.x;
    const int lane = tid & 31;
    const int wid = tid >> 5;
    const int warpM = wid >> 2, warpN = wid & 3;
    const int bm = blockIdx.y * 128;
    const int bn = blockIdx.x * 128;

    const int chunk = lane & 7;
    const int kstep = chunk >> 1;
    const int k4 = chunk & 1;
    const int kpair = kstep >> 1;
    const int rbase = (((lane >> 3) & 1)) | ((wid & 3) << 1) | (((lane >> 4) & 1) << 3) | ((wid >> 2) << 4);

    float acc[4][4][4];
    #pragma unroll
    for (int i = 0; i < 4; i++)
        #pragma unroll
        for (int j = 0; j < 4; j++)
            #pragma unroll
            for (int r = 0; r < 4; r++) acc[i][j][r] = 0.f;

    const int nk = K >> 5;
    float4 ra[4], rb[4];

    #pragma unroll
    for (int lp = 0; lp < 4; lp++) {
        int r = rbase + (lp << 5);
        ra[lp] = *reinterpret_cast<const float4*>(A + (size_t)(bm + r) * K + chunk * 4);
        rb[lp] = *reinterpret_cast<const float4*>(W + (size_t)(bn + r) * K + chunk * 4);
    }

    for (int kt = 0; kt < nk; kt++) {
        __syncthreads();
        #pragma unroll
        for (int lp = 0; lp < 4; lp++) {
            int r = rbase + (lp << 5);
            int aIdx = kstep * 1028 + (r >> 4) * 128 + (r & 7) * 16 + ((r >> 3) & 1) + 2 * k4;
            int bIdx = kpair * 2120 + (r >> 3) * 132 + (r & 7) * 16 + 2 * (kstep & 1) + k4;
            float av[4] = {ra[lp].x, ra[lp].y, ra[lp].z, ra[lp].w};
            float bv[4] = {rb[lp].x, rb[lp].y, rb[lp].z, rb[lp].w};
            #pragma unroll
            for (int c = 0; c < 4; c++) {
                Aw[aIdx + 4 * c] = f2tf32(av[c]);
                Bw[bIdx + 4 * c] = f2tf32(bv[c]);
            }
        }
        __syncthreads();

        if (kt + 1 < nk) {
            int k0 = (kt + 1) << 5;
            #pragma unroll
            for (int lp = 0; lp < 4; lp++) {
                int r = rbase + (lp << 5);
                ra[lp] = *reinterpret_cast<const float4*>(A + (size_t)(bm + r) * K + k0 + chunk * 4);
                rb[lp] = *reinterpret_cast<const float4*>(W + (size_t)(bn + r) * K + k0 + chunk * 4);
            }
        }

        uint4 bf[2][4];
        #pragma unroll
        for (int kp = 0; kp < 2; kp++)
            #pragma unroll
            for (int j = 0; j < 4; j++)
                bf[kp][j] = *reinterpret_cast<const uint4*>(&Bw[kp * 2120 + (warpN * 4 + j) * 132 + lane * 4]);

        #pragma unroll
        for (int ks = 0; ks < 4; ks++) {
            uint4 af[4];
            #pragma unroll
            for (int i = 0; i < 4; i++)
                af[i] = *reinterpret_cast<const uint4*>(&Aw[ks * 1028 + (warpM * 4 + i) * 128 + lane * 4]);
            const int kp = ks >> 1, odd = ks & 1;
            #pragma unroll
            for (int i = 0; i < 4; i++)
                #pragma unroll
                for (int j = 0; j < 4; j++) {
                    uint32_t b0 = odd ? bf[kp][j].z : bf[kp][j].x;
                    uint32_t b1 = odd ? bf[kp][j].w : bf[kp][j].y;
                    mma8(acc[i][j], af[i], b0, b1);
                }
        }
    }

    const int gid = lane >> 2, tig = lane & 3;
    #pragma unroll
    for (int i = 0; i < 4; i++) {
        int row0 = bm + warpM * 64 + i * 16 + gid;
        #pragma unroll
        for (int j = 0; j < 4; j++) {
            int col = bn + warpN * 32 + j * 8 + tig * 2;
            float b0 = bias[col], b1 = bias[col + 1];
            float v0 = acc[i][j][0] + b0;
            float v1 = acc[i][j][1] + b1;
            float v2 = acc[i][j][2] + b0;
            float v3 = acc[i][j][3] + b1;
            if (EPI == 1) { v0 = gelu_f(v0); v1 = gelu_f(v1); v2 = gelu_f(v2); v3 = gelu_f(v3); }
            if (res) {
                v0 += res[(size_t)row0 * N + col];
                v1 += res[(size_t)row0 * N + col + 1];
                v2 += res[(size_t)(row0 + 8) * N + col];
                v3 += res[(size_t)(row0 + 8) * N + col + 1];
            }
            *reinterpret_cast<float2*>(C + (size_t)row0 * N + col)       = make_float2(v0, v1);
            *reinterpret_cast<float2*>(C + (size_t)(row0 + 8) * N + col) = make_float2(v2, v3);
        }
    }
}

template <int EPI>
__global__ __launch_bounds__(256)
void gemm_tc(const float* __restrict__ A, const float* __restrict__ W,
             const float* __restrict__ bias, const float* __restrict__ res,
             float* __restrict__ C, int M, int N, int K)
{
    gemm_body<EPI>(A, W, bias, res, C, M, N, K);
}

// fused QKV: grid.z selects projection
__global__ __launch_bounds__(256)
void gemm_qkv(const float* __restrict__ A,
              const float* __restrict__ Wq, const float* __restrict__ Wk, const float* __restrict__ Wv,
              const float* __restrict__ bq, const float* __restrict__ bk, const float* __restrict__ bv,
              float* __restrict__ q, float* __restrict__ k, float* __restrict__ v)
{
    const int z = blockIdx.z;
    const float* W = (z == 0) ? Wq : (z == 1) ? Wk : Wv;
    const float* bias = (z == 0) ? bq : (z == 1) ? bk : bv;
    float* C = (z == 0) ? q : (z == 1) ? k : v;
    gemm_body<0>(A, W, bias, nullptr, C, MROWS, EMB, EMB);
}

// ================= V transpose per head: vt[bh][d][s] = v[b][s][h*64+d] =================
__global__ __launch_bounds__(256)
void transpose_v_k(const float* __restrict__ v, float* __restrict__ vt)
{
    __shared__ float t[32][33];
    const int bh = blockIdx.z;
    const int b = bh >> 4, h = bh & 15;
    const int s0 = blockIdx.x * 32;
    const int d0 = blockIdx.y * 32;
    const int x = threadIdx.x & 31;
    const int y0 = threadIdx.x >> 5;

    #pragma unroll
    for (int j = 0; j < 4; j++) {
        int sr = y0 + j * 8;
        t[sr][x] = v[((size_t)(b * SEQ + s0 + sr)) * EMB + h * HD + d0 + x];
    }
    __syncthreads();
    #pragma unroll
    for (int j = 0; j < 4; j++) {
        int dr = y0 + j * 8;
        vt[((size_t)bh * HD + d0 + dr) * SEQ + s0 + x] = t[x][dr];
    }
}

// ================= Fused flash attention =================
// One CTA per (bh, 128 q rows). No score buffer, no softmax kernel.
// smem word layout:
//   QA  [0,      8224)  : Q frag-layout, 2 k-tiles of 32
//   KVB [8224,  16736)  : K tiles (2 x 4240) then reused for V tiles (4 x 2128)
//   PA  [16736, 33184)  : P frag-layout, 4 k-tiles of 32
//   RM  [33184, 33696)  : rowmax [128][4]
//   RS  [33696, 34208)  : rowsum [128][4]
#define FA_QA   0
#define FA_KVB  8224
#define FA_PA   16736
#define FA_RM   33184
#define FA_RS   33696
#define FA_SMEM_BYTES (34208 * 4)

__global__ __launch_bounds__(256)
void flash_attn(const float* __restrict__ q, const float* __restrict__ kk,
                const float* __restrict__ vt, const int* __restrict__ mask,
                float* __restrict__ o)
{
    extern __shared__ uint32_t dyn[];
    uint32_t* QA  = dyn + FA_QA;
    uint32_t* KVB = dyn + FA_KVB;
    uint32_t* PA  = dyn + FA_PA;
    float*    RM  = reinterpret_cast<float*>(dyn + FA_RM);
    float*    RS  = reinterpret_cast<float*>(dyn + FA_RS);

    const int tid = threadIdx.x;
    const int lane = tid & 31;
    const int wid = tid >> 5;
    const int warpM = wid >> 2, warpN = wid & 3;
    const int gid = lane >> 2, tig = lane & 3;
    const int bh = blockIdx.y;
    const int b = bh >> 4, h = bh & 15;
    const int bm = blockIdx.x * 128;

    const int chunk = lane & 7;
    const int kstep = chunk >> 1;
    const int k4 = chunk & 1;
    const int kpair = kstep >> 1;
    const int rbase = (((lane >> 3) & 1)) | ((wid & 3) << 1) | (((lane >> 4) & 1) << 3) | ((wid >> 2) << 4);

    int aIdx[4], bIdx[4], bIdx64[2];
    #pragma unroll
    for (int lp = 0; lp < 4; lp++) {
        int r = rbase + (lp << 5);
        aIdx[lp] = kstep * 1028 + (r >> 4) * 128 + (r & 7) * 16 + ((r >> 3) & 1) + 2 * k4;
        bIdx[lp] = kpair * 2120 + (r >> 3) * 132 + (r & 7) * 16 + 2 * (kstep & 1) + k4;
    }
    #pragma unroll
    for (int lp = 0; lp < 2; lp++) {
        int r = rbase + (lp << 5);
        bIdx64[lp] = kpair * 1064 + (r >> 3) * 132 + (r & 7) * 16 + 2 * (kstep & 1) + k4;
    }

    const float* qptr = q  + (size_t)(b * SEQ + bm) * EMB + h * HD;
    const float* kptr = kk + (size_t)(b * SEQ) * EMB + h * HD;
    const float* vptr = vt + (size_t)bh * HD * SEQ;

    // stage Q once (both 32-k tiles)
    #pragma unroll
    for (int ktq = 0; ktq < 2; ktq++) {
        #pragma unroll
        for (int lp = 0; lp < 4; lp++) {
            int r = rbase + (lp << 5);
            float4 f = *reinterpret_cast<const float4*>(qptr + (size_t)r * EMB + ktq * 32 + chunk * 4);
            float av[4] = {f.x, f.y, f.z, f.w};
            #pragma unroll
            for (int c = 0; c < 4; c++)
                QA[ktq * 4112 + aIdx[lp] + 4 * c] = f2tf32(av[c]);
        }
    }

    float m_run[4][2], l_run[4][2];
    float acc_o[4][2][4];
    #pragma unroll
    for (int i = 0; i < 4; i++)
        #pragma unroll
        for (int h2 = 0; h2 < 2; h2++) { m_run[i][h2] = -3e38f; l_run[i][h2] = 0.f; }
    #pragma unroll
    for (int i = 0; i < 4; i++)
        #pragma unroll
        for (int j = 0; j < 2; j++)
            #pragma unroll
            for (int r = 0; r < 4; r++) acc_o[i][j][r] = 0.f;

    for (int kt = 0; kt < SEQ / 128; kt++) {
        const int kbase = kt * 128;

        // stage K tile (128 rows x 64 d) as two 32-k B128 tiles
        #pragma unroll
        for (int ktk = 0; ktk < 2; ktk++) {
            #pragma unroll
            for (int lp = 0; lp < 4; lp++) {
                int r = rbase + (lp << 5);
                float4 f = *reinterpret_cast<const float4*>(
                    kptr + (size_t)(kbase + r) * EMB + ktk * 32 + chunk * 4);
                float bv[4] = {f.x, f.y, f.z, f.w};
                #pragma unroll
                for (int c = 0; c < 4; c++)
                    KVB[ktk * 4240 + bIdx[lp] + 4 * c] = f2tf32(bv[c]);
            }
        }
        __syncthreads();

        // S = Q K^T
        float accs[4][4][4];
        #pragma unroll
        for (int i = 0; i < 4; i++)
            #pragma unroll
            for (int j = 0; j < 4; j++)
                #pragma unroll
                for (int r = 0; r < 4; r++) accs[i][j][r] = 0.f;

        #pragma unroll
        for (int ktile = 0; ktile < 2; ktile++) {
            uint4 bf[2][4];
            #pragma unroll
            for (int kp = 0; kp < 2; kp++)
                #pragma unroll
                for (int j = 0; j < 4; j++)
                    bf[kp][j] = *reinterpret_cast<const uint4*>(
                        &KVB[ktile * 4240 + kp * 2120 + (warpN * 4 + j) * 132 + lane * 4]);
            #pragma unroll
            for (int ks = 0; ks < 4; ks++) {
                uint4 af[4];
                #pragma unroll
                for (int i = 0; i < 4; i++)
                    af[i] = *reinterpret_cast<const uint4*>(
                        &QA[ktile * 4112 + ks * 1028 + (warpM * 4 + i) * 128 + lane * 4]);
                const int kp = ks >> 1, odd = ks & 1;
                #pragma unroll
                for (int i = 0; i < 4; i++)
                    #pragma unroll
                    for (int j = 0; j < 4; j++) {
                        uint32_t b0 = odd ? bf[kp][j].z : bf[kp][j].x;
                        uint32_t b1 = odd ? bf[kp][j].w : bf[kp][j].y;
                        mma8(accs[i][j], af[i], b0, b1);
                    }
            }
        }

        // mask + scale
        #pragma unroll
        for (int i = 0; i < 4; i++) {
            int row0 = bm + warpM * 64 + i * 16 + gid;
            #pragma unroll
            for (int j = 0; j < 4; j++) {
                int col = kbase + warpN * 32 + j * 8 + tig * 2;
                int2 m0 = *reinterpret_cast<const int2*>(&mask[((size_t)b * SEQ + row0) * SEQ + col]);
                int2 m1 = *reinterpret_cast<const int2*>(&mask[((size_t)b * SEQ + row0 + 8) * SEQ + col]);
                accs[i][j][0] = m0.x ? accs[i][j][0] * 0.125f : -0.01f;
                accs[i][j][1] = m0.y ? accs[i][j][1] * 0.125f : -0.01f;
                accs[i][j][2] = m1.x ? accs[i][j][2] * 0.125f : -0.01f;
                accs[i][j][3] = m1.y ? accs[i][j][3] * 0.125f : -0.01f;
            }
        }

        // tile row max -> smem
        #pragma unroll
        for (int i = 0; i < 4; i++) {
            #pragma unroll
            for (int h2 = 0; h2 < 2; h2++) {
                float mx = -3e38f;
                #pragma unroll
                for (int j = 0; j < 4; j++)
                    mx = fmaxf(mx, fmaxf(accs[i][j][h2 * 2], accs[i][j][h2 * 2 + 1]));
                mx = fmaxf(mx, __shfl_xor_sync(0xffffffffu, mx, 1));
                mx = fmaxf(mx, __shfl_xor_sync(0xffffffffu, mx, 2));
                if (tig == 0)
                    RM[(warpM * 64 + i * 16 + gid + 8 * h2) * 4 + warpN] = mx;
            }
        }
        __syncthreads();

        // combine with running stats; rescale O
        float scl[4][2];
        #pragma unroll
        for (int i = 0; i < 4; i++) {
            #pragma unroll
            for (int h2 = 0; h2 < 2; h2++) {
                int rowl = warpM * 64 + i * 16 + gid + 8 * h2;
                float tm = fmaxf(fmaxf(RM[rowl * 4 + 0], RM[rowl * 4 + 1]),
                                 fmaxf(RM[rowl * 4 + 2], RM[rowl * 4 + 3]));
                float mn = fmaxf(m_run[i][h2], tm);
                scl[i][h2] = __expf(m_run[i][h2] - mn);
                m_run[i][h2] = mn;
                l_run[i][h2] *= scl[i][h2];
            }
        }
        #pragma unroll
        for (int i = 0; i < 4; i++)
            #pragma unroll
            for (int j = 0; j < 2; j++) {
                acc_o[i][j][0] *= scl[i][0];
                acc_o[i][j][1] *= scl[i][0];
                acc_o[i][j][2] *= scl[i][1];
                acc_o[i][j][3] *= scl[i][1];
            }

        // p = exp(s - m); partial row sums; stage P into PA
        float tsum[4][2];
        #pragma unroll
        for (int i = 0; i < 4; i++) { tsum[i][0] = 0.f; tsum[i][1] = 0.f; }

        #pragma unroll
        for (int i = 0; i < 4; i++) {
            #pragma unroll
            for (int j = 0; j < 4; j++) {
                #pragma unroll
                for (int r = 0; r < 4; r++) {
                    const int h2 = r >> 1;
                    float p = __expf(accs[i][j][r] - m_run[i][h2]);
                    accs[i][j][r] = p;
                    tsum[i][h2] += p;
                    int word = warpN * 4112 + j * 1028 + (warpM * 4 + i) * 128 + gid * 16
                             + h2 + 2 * (tig >> 1) + 4 * ((2 * tig + (r & 1)) & 3);
                    PA[word] = f2tf32(p);
                }
            }
        }
        #pragma unroll
        for (int i = 0; i < 4; i++) {
            #pragma unroll
            for (int h2 = 0; h2 < 2; h2++) {
                float sv = tsum[i][h2];
                sv += __shfl_xor_sync(0xffffffffu, sv, 1);
                sv += __shfl_xor_sync(0xffffffffu, sv, 2);
                if (tig == 0)
                    RS[(warpM * 64 + i * 16 + gid + 8 * h2) * 4 + warpN] = sv;
            }
        }

        // stage V tile into KVB (K reads finished before the last sync)
        #pragma unroll
        for (int ktv = 0; ktv < 4; ktv++) {
            #pragma unroll
            for (int lp = 0; lp < 2; lp++) {
                int r = rbase + (lp << 5);   // d row 0..63
                float4 f = *reinterpret_cast<const float4*>(
                    vptr + (size_t)r * SEQ + kbase + ktv * 32 + chunk * 4);
                float bv[4] = {f.x, f.y, f.z, f.w};
                #pragma unroll
                for (int c = 0; c < 4; c++)
                    KVB[ktv * 2128 + bIdx64[lp] + 4 * c] = f2tf32(bv[c]);
            }
        }
        __syncthreads();

        // l update
        #pragma unroll
        for (int i = 0; i < 4; i++) {
            #pragma unroll
            for (int h2 = 0; h2 < 2; h2++) {
                int rowl = warpM * 64 + i * 16 + gid + 8 * h2;
                l_run[i][h2] += RS[rowl * 4 + 0] + RS[rowl * 4 + 1]
                              + RS[rowl * 4 + 2] + RS[rowl * 4 + 3];
            }
        }

        // O += P V
        #pragma unroll
        for (int ktv = 0; ktv < 4; ktv++) {
            uint4 bf[2][2];
            #pragma unroll
            for (int kp = 0; kp < 2; kp++)
                #pragma unroll
                for (int j = 0; j < 2; j++)
                    bf[kp][j] = *reinterpret_cast<const uint4*>(
                        &KVB[ktv * 2128 + kp * 1064 + (warpN * 2 + j) * 132 + lane * 4]);
            #pragma unroll
            for (int ks = 0; ks < 4; ks++) {
                uint4 af[4];
                #pragma unroll
                for (int i = 0; i < 4; i++)
                    af[i] = *reinterpret_cast<const uint4*>(
                        &PA[ktv * 4112 + ks * 1028 + (warpM * 4 + i) * 128 + lane * 4]);
                const int kp = ks >> 1, odd = ks & 1;
                #pragma unroll
                for (int i = 0; i < 4; i++)
                    #pragma unroll
                    for (int j = 0; j < 2; j++) {
                        uint32_t b0 = odd ? bf[kp][j].z : bf[kp][j].x;
                        uint32_t b1 = odd ? bf[kp][j].w : bf[kp][j].y;
                        mma8(acc_o[i][j], af[i], b0, b1);
                    }
            }
        }
        __syncthreads();   // protect KVB/PA reuse next iteration
    }

    // epilogue: O / l
    #pragma unroll
    for (int i = 0; i < 4; i++) {
        int row0 = bm + warpM * 64 + i * 16 + gid;
        float inv0 = 1.0f / l_run[i][0];
        float inv1 = 1.0f / l_run[i][1];
        #pragma unroll
        for (int j = 0; j < 2; j++) {
            int col = warpN * 16 + j * 8 + tig * 2;
            *reinterpret_cast<float2*>(o + ((size_t)(b * SEQ + row0)) * EMB + h * HD + col) =
                make_float2(acc_o[i][j][0] * inv0, acc_o[i][j][1] * inv0);
            *reinterpret_cast<float2*>(o + ((size_t)(b * SEQ + row0 + 8)) * EMB + h * HD + col) =
                make_float2(acc_o[i][j][2] * inv1, acc_o[i][j][3] * inv1);
        }
    }
}

// ---------------- launch ----------------
extern "C" void kernel_launch(void* const* d_in, const int* in_sizes, int n_in,
                              void* d_out, int out_size)
{
    const float* x   = (const float*)d_in[0];
    const int*   mask= (const int*)  d_in[1];
    const float* Wq  = (const float*)d_in[2];
    const float* bq  = (const float*)d_in[3];
    const float* Wk  = (const float*)d_in[4];
    const float* bk  = (const float*)d_in[5];
    const float* Wv  = (const float*)d_in[6];
    const float* bv  = (const float*)d_in[7];
    const float* Wo  = (const float*)d_in[8];
    const float* bo  = (const float*)d_in[9];
    const float* W1  = (const float*)d_in[10];
    const float* b1  = (const float*)d_in[11];
    const float* W2  = (const float*)d_in[12];
    const float* b2  = (const float*)d_in[13];
    const float* g1  = (const float*)d_in[14];
    const float* be1 = (const float*)d_in[15];
    const float* g2  = (const float*)d_in[16];
    const float* be2 = (const float*)d_in[17];
    float* out = (float*)d_out;

    float *nx, *q, *k, *v, *vt, *o, *x1, *nx2, *hbuf;
    cudaGetSymbolAddress((void**)&nx,   g_nx);
    cudaGetSymbolAddress((void**)&q,    g_q);
    cudaGetSymbolAddress((void**)&k,    g_k);
    cudaGetSymbolAddress((void**)&v,    g_v);
    cudaGetSymbolAddress((void**)&vt,   g_vt);
    cudaGetSymbolAddress((void**)&o,    g_o);
    cudaGetSymbolAddress((void**)&x1,   g_x1);
    cudaGetSymbolAddress((void**)&nx2,  g_nx2);
    cudaGetSymbolAddress((void**)&hbuf, g_h);

    cudaFuncSetAttribute(flash_attn, cudaFuncAttributeMaxDynamicSharedMemorySize, FA_SMEM_BYTES);

    const dim3 gEE(EMB / 128, MROWS / 128);
    const dim3 gFF(DFF / 128, MROWS / 128);

    layernorm_k<<<MROWS, 256>>>(x, g1, be1, nx);
    gemm_qkv<<<dim3(EMB / 128, MROWS / 128, 3), 256>>>(nx, Wq, Wk, Wv, bq, bk, bv, q, k, v);

    transpose_v_k<<<dim3(SEQ / 32, HD / 32, BB * NH), 256>>>(v, vt);
    flash_attn<<<dim3(SEQ / 128, BB * NH), 256, FA_SMEM_BYTES>>>(q, k, vt, mask, o);

    gemm_tc<0><<<gEE, 256>>>(o, Wo, bo, x, x1, MROWS, EMB, EMB);
    layernorm_k<<<MROWS, 256>>>(x1, g2, be2, nx2);
    gemm_tc<1><<<gFF, 256>>>(nx2, W1, b1, nullptr, hbuf, MROWS, DFF, EMB);
    gemm_tc<0><<<gEE, 256>>>(hbuf, W2, b2, x1, out, MROWS, EMB, DFF);
}

// round 11
// speedup vs baseline: 1.1893x; 1.0378x over previous
#include <cuda_runtime.h>
#include <math.h>
#include <stdint.h>

#define BB   4
#define SEQ  1024
#define EMB  1024
#define NH   16
#define HD   64
#define DFF  4096
#define MROWS (BB*SEQ)   // 4096

// ---------------- scratch (static device globals; no allocation) ----------------
__device__ float g_nx [MROWS*EMB];
__device__ float g_q  [MROWS*EMB];
__device__ float g_k  [MROWS*EMB];
__device__ float g_v  [MROWS*EMB];
__device__ float g_vt [BB*NH*HD*SEQ];   // V transposed per head: [bh][d][seq]
__device__ float g_o  [MROWS*EMB];
__device__ float g_x1 [MROWS*EMB];
__device__ float g_nx2[MROWS*EMB];
__device__ float g_h  [MROWS*DFF];

// ---------------- helpers ----------------
__device__ __forceinline__ uint32_t f2tf32(float f) {
    uint32_t u;
    asm("cvt.rna.tf32.f32 %0, %1;" : "=r"(u) : "f"(f));
    return u;
}

__device__ __forceinline__ void mma8(float c[4], const uint4& a, uint32_t b0, uint32_t b1) {
    asm volatile(
        "mma.sync.aligned.m16n8k8.row.col.f32.tf32.tf32.f32 "
        "{%0,%1,%2,%3},{%4,%5,%6,%7},{%8,%9},{%0,%1,%2,%3};"
        : "+f"(c[0]), "+f"(c[1]), "+f"(c[2]), "+f"(c[3])
        : "r"(a.x), "r"(a.y), "r"(a.z), "r"(a.w), "r"(b0), "r"(b1));
}

__device__ __forceinline__ float gelu_f(float x) {
    const float c = 0.7978845608028654f;  // sqrt(2/pi)
    float t = tanhf(c * (x + 0.044715f * x * x * x));
    return 0.5f * x * (1.0f + t);
}

// Frag-order staging layouts (conflict-free; bank-verified in R4):
// A (128 rows, 32 k): word = kstep*1028 + m16*128 + (m&7)*16 + ((m>>3)&1) + 2*k4 + 4*c
// B128 (128 rows, 32 k): word = kpair*2120 + n8*132 + (n&7)*16 + 2*(kstep&1) + k4 + 4*c
// B64  ( 64 rows, 32 k): kpair stride 1064
#define A_WORDS 4112
#define B_WORDS_128 4240
#define B_WORDS_64  2128

// ---------------- LayerNorm (one block per row of 1024) ----------------
__global__ __launch_bounds__(256)
void layernorm_k(const float* __restrict__ x, const float* __restrict__ g,
                 const float* __restrict__ b, float* __restrict__ out)
{
    __shared__ float red[8];
    const int row = blockIdx.x;
    const int tid = threadIdx.x;
    const float* xr = x + (size_t)row * EMB;

    float4 f = reinterpret_cast<const float4*>(xr)[tid];

    float s = f.x + f.y + f.z + f.w;
    #pragma unroll
    for (int o = 16; o > 0; o >>= 1) s += __shfl_xor_sync(0xffffffffu, s, o);
    if ((tid & 31) == 0) red[tid >> 5] = s;
    __syncthreads();
    float mean = 0.f;
    #pragma unroll
    for (int i = 0; i < 8; i++) mean += red[i];
    mean *= (1.0f / (float)EMB);
    __syncthreads();

    float dx0 = f.x - mean, dx1 = f.y - mean, dx2 = f.z - mean, dx3 = f.w - mean;
    float ss = dx0*dx0 + dx1*dx1 + dx2*dx2 + dx3*dx3;
    #pragma unroll
    for (int o = 16; o > 0; o >>= 1) ss += __shfl_xor_sync(0xffffffffu, ss, o);
    if ((tid & 31) == 0) red[tid >> 5] = ss;
    __syncthreads();
    float var = 0.f;
    #pragma unroll
    for (int i = 0; i < 8; i++) var += red[i];
    var *= (1.0f / (float)(EMB - 1));
    const float rs = 1.0f / (sqrtf(var) + 1e-8f);

    const float4 gg = reinterpret_cast<const float4*>(g)[tid];
    const float4 bb = reinterpret_cast<const float4*>(b)[tid];
    float4 r;
    r.x = gg.x * dx0 * rs + bb.x;
    r.y = gg.y * dx1 * rs + bb.y;
    r.z = gg.z * dx2 * rs + bb.z;
    r.w = gg.w * dx3 * rs + bb.w;
    reinterpret_cast<float4*>(out + (size_t)row * EMB)[tid] = r;
}

// ================= tf32 mma.sync GEMM body =================
// 2 CTAs/SM target: no cross-ktile prefetch registers, B frags loaded per even-ks.
template <int EPI>   // 0 = none, 1 = gelu
__device__ __forceinline__
void gemm_body(const float* __restrict__ A, const float* __restrict__ W,
               const float* __restrict__ bias, const float* __restrict__ res,
               float* __restrict__ C, int M, int N, int K)
{
    __shared__ uint32_t Aw[A_WORDS];
    __shared__ uint32_t Bw[B_WORDS_128];

    const int tid = threadIdx.x;
    const int lane = tid & 31;
    const int wid = tid >> 5;
    const int warpM = wid >> 2, warpN = wid & 3;
    const int bm = blockIdx.y * 128;
    const int bn = blockIdx.x * 128;

    const int chunk = lane & 7;
    const int kstep = chunk >> 1;
    const int k4 = chunk & 1;
    const int kpair = kstep >> 1;
    const int rbase = (((lane >> 3) & 1)) | ((wid & 3) << 1) | (((lane >> 4) & 1) << 3) | ((wid >> 2) << 4);

    int aIdx[4], bIdx[4];
    #pragma unroll
    for (int lp = 0; lp < 4; lp++) {
        int r = rbase + (lp << 5);
        aIdx[lp] = kstep * 1028 + (r >> 4) * 128 + (r & 7) * 16 + ((r >> 3) & 1) + 2 * k4;
        bIdx[lp] = kpair * 2120 + (r >> 3) * 132 + (r & 7) * 16 + 2 * (kstep & 1) + k4;
    }

    float acc[4][4][4];
    #pragma unroll
    for (int i = 0; i < 4; i++)
        #pragma unroll
        for (int j = 0; j < 4; j++)
            #pragma unroll
            for (int r = 0; r < 4; r++) acc[i][j][r] = 0.f;

    const int nk = K >> 5;

    for (int kt = 0; kt < nk; kt++) {
        const int k0 = kt << 5;
        __syncthreads();
        // LDG -> cvt -> STS (latency hidden by the co-resident CTA's MMA phase)
        #pragma unroll
        for (int lp = 0; lp < 4; lp++) {
            int r = rbase + (lp << 5);
            float4 fa = *reinterpret_cast<const float4*>(A + (size_t)(bm + r) * K + k0 + chunk * 4);
            float4 fw = *reinterpret_cast<const float4*>(W + (size_t)(bn + r) * K + k0 + chunk * 4);
            float av[4] = {fa.x, fa.y, fa.z, fa.w};
            float bv[4] = {fw.x, fw.y, fw.z, fw.w};
            #pragma unroll
            for (int c = 0; c < 4; c++) {
                Aw[aIdx[lp] + 4 * c] = f2tf32(av[c]);
                Bw[bIdx[lp] + 4 * c] = f2tf32(bv[c]);
            }
        }
        __syncthreads();

        uint4 bf[4];
        #pragma unroll
        for (int ks = 0; ks < 4; ks++) {
            const int kp = ks >> 1, odd = ks & 1;
            if (!odd) {
                #pragma unroll
                for (int j = 0; j < 4; j++)
                    bf[j] = *reinterpret_cast<const uint4*>(&Bw[kp * 2120 + (warpN * 4 + j) * 132 + lane * 4]);
            }
            uint4 af[4];
            #pragma unroll
            for (int i = 0; i < 4; i++)
                af[i] = *reinterpret_cast<const uint4*>(&Aw[ks * 1028 + (warpM * 4 + i) * 128 + lane * 4]);
            #pragma unroll
            for (int i = 0; i < 4; i++)
                #pragma unroll
                for (int j = 0; j < 4; j++) {
                    uint32_t b0 = odd ? bf[j].z : bf[j].x;
                    uint32_t b1 = odd ? bf[j].w : bf[j].y;
                    mma8(acc[i][j], af[i], b0, b1);
                }
        }
    }

    const int gid = lane >> 2, tig = lane & 3;
    #pragma unroll
    for (int i = 0; i < 4; i++) {
        int row0 = bm + warpM * 64 + i * 16 + gid;
        #pragma unroll
        for (int j = 0; j < 4; j++) {
            int col = bn + warpN * 32 + j * 8 + tig * 2;
            float b0 = bias[col], b1 = bias[col + 1];
            float v0 = acc[i][j][0] + b0;
            float v1 = acc[i][j][1] + b1;
            float v2 = acc[i][j][2] + b0;
            float v3 = acc[i][j][3] + b1;
            if (EPI == 1) { v0 = gelu_f(v0); v1 = gelu_f(v1); v2 = gelu_f(v2); v3 = gelu_f(v3); }
            if (res) {
                v0 += res[(size_t)row0 * N + col];
                v1 += res[(size_t)row0 * N + col + 1];
                v2 += res[(size_t)(row0 + 8) * N + col];
                v3 += res[(size_t)(row0 + 8) * N + col + 1];
            }
            *reinterpret_cast<float2*>(C + (size_t)row0 * N + col)       = make_float2(v0, v1);
            *reinterpret_cast<float2*>(C + (size_t)(row0 + 8) * N + col) = make_float2(v2, v3);
        }
    }
}

template <int EPI>
__global__ __launch_bounds__(256, 2)
void gemm_tc(const float* __restrict__ A, const float* __restrict__ W,
             const float* __restrict__ bias, const float* __restrict__ res,
             float* __restrict__ C, int M, int N, int K)
{
    gemm_body<EPI>(A, W, bias, res, C, M, N, K);
}

// fused QKV: grid.z selects projection
__global__ __launch_bounds__(256, 2)
void gemm_qkv(const float* __restrict__ A,
              const float* __restrict__ Wq, const float* __restrict__ Wk, const float* __restrict__ Wv,
              const float* __restrict__ bq, const float* __restrict__ bk, const float* __restrict__ bv,
              float* __restrict__ q, float* __restrict__ k, float* __restrict__ v)
{
    const int z = blockIdx.z;
    const float* W = (z == 0) ? Wq : (z == 1) ? Wk : Wv;
    const float* bias = (z == 0) ? bq : (z == 1) ? bk : bv;
    float* C = (z == 0) ? q : (z == 1) ? k : v;
    gemm_body<0>(A, W, bias, nullptr, C, MROWS, EMB, EMB);
}

// ================= V transpose per head: vt[bh][d][s] = v[b][s][h*64+d] =================
__global__ __launch_bounds__(256)
void transpose_v_k(const float* __restrict__ v, float* __restrict__ vt)
{
    __shared__ float t[32][33];
    const int bh = blockIdx.z;
    const int b = bh >> 4, h = bh & 15;
    const int s0 = blockIdx.x * 32;
    const int d0 = blockIdx.y * 32;
    const int x = threadIdx.x & 31;
    const int y0 = threadIdx.x >> 5;

    #pragma unroll
    for (int j = 0; j < 4; j++) {
        int sr = y0 + j * 8;
        t[sr][x] = v[((size_t)(b * SEQ + s0 + sr)) * EMB + h * HD + d0 + x];
    }
    __syncthreads();
    #pragma unroll
    for (int j = 0; j < 4; j++) {
        int dr = y0 + j * 8;
        vt[((size_t)bh * HD + d0 + dr) * SEQ + s0 + x] = t[x][dr];
    }
}

// ================= Fused flash attention (unchanged from R10) =================
#define FA_QA   0
#define FA_KVB  8224
#define FA_PA   16736
#define FA_RM   33184
#define FA_RS   33696
#define FA_SMEM_BYTES (34208 * 4)

__global__ __launch_bounds__(256)
void flash_attn(const float* __restrict__ q, const float* __restrict__ kk,
                const float* __restrict__ vt, const int* __restrict__ mask,
                float* __restrict__ o)
{
    extern __shared__ uint32_t dyn[];
    uint32_t* QA  = dyn + FA_QA;
    uint32_t* KVB = dyn + FA_KVB;
    uint32_t* PA  = dyn + FA_PA;
    float*    RM  = reinterpret_cast<float*>(dyn + FA_RM);
    float*    RS  = reinterpret_cast<float*>(dyn + FA_RS);

    const int tid = threadIdx.x;
    const int lane = tid & 31;
    const int wid = tid >> 5;
    const int warpM = wid >> 2, warpN = wid & 3;
    const int gid = lane >> 2, tig = lane & 3;
    const int bh = blockIdx.y;
    const int b = bh >> 4, h = bh & 15;
    const int bm = blockIdx.x * 128;

    const int chunk = lane & 7;
    const int kstep = chunk >> 1;
    const int k4 = chunk & 1;
    const int kpair = kstep >> 1;
    const int rbase = (((lane >> 3) & 1)) | ((wid & 3) << 1) | (((lane >> 4) & 1) << 3) | ((wid >> 2) << 4);

    int aIdx[4], bIdx[4], bIdx64[2];
    #pragma unroll
    for (int lp = 0; lp < 4; lp++) {
        int r = rbase + (lp << 5);
        aIdx[lp] = kstep * 1028 + (r >> 4) * 128 + (r & 7) * 16 + ((r >> 3) & 1) + 2 * k4;
        bIdx[lp] = kpair * 2120 + (r >> 3) * 132 + (r & 7) * 16 + 2 * (kstep & 1) + k4;
    }
    #pragma unroll
    for (int lp = 0; lp < 2; lp++) {
        int r = rbase + (lp << 5);
        bIdx64[lp] = kpair * 1064 + (r >> 3) * 132 + (r & 7) * 16 + 2 * (kstep & 1) + k4;
    }

    const float* qptr = q  + (size_t)(b * SEQ + bm) * EMB + h * HD;
    const float* kptr = kk + (size_t)(b * SEQ) * EMB + h * HD;
    const float* vptr = vt + (size_t)bh * HD * SEQ;

    #pragma unroll
    for (int ktq = 0; ktq < 2; ktq++) {
        #pragma unroll
        for (int lp = 0; lp < 4; lp++) {
            int r = rbase + (lp << 5);
            float4 f = *reinterpret_cast<const float4*>(qptr + (size_t)r * EMB + ktq * 32 + chunk * 4);
            float av[4] = {f.x, f.y, f.z, f.w};
            #pragma unroll
            for (int c = 0; c < 4; c++)
                QA[ktq * 4112 + aIdx[lp] + 4 * c] = f2tf32(av[c]);
        }
    }

    float m_run[4][2], l_run[4][2];
    float acc_o[4][2][4];
    #pragma unroll
    for (int i = 0; i < 4; i++)
        #pragma unroll
        for (int h2 = 0; h2 < 2; h2++) { m_run[i][h2] = -3e38f; l_run[i][h2] = 0.f; }
    #pragma unroll
    for (int i = 0; i < 4; i++)
        #pragma unroll
        for (int j = 0; j < 2; j++)
            #pragma unroll
            for (int r = 0; r < 4; r++) acc_o[i][j][r] = 0.f;

    for (int kt = 0; kt < SEQ / 128; kt++) {
        const int kbase = kt * 128;

        #pragma unroll
        for (int ktk = 0; ktk < 2; ktk++) {
            #pragma unroll
            for (int lp = 0; lp < 4; lp++) {
                int r = rbase + (lp << 5);
                float4 f = *reinterpret_cast<const float4*>(
                    kptr + (size_t)(kbase + r) * EMB + ktk * 32 + chunk * 4);
                float bv[4] = {f.x, f.y, f.z, f.w};
                #pragma unroll
                for (int c = 0; c < 4; c++)
                    KVB[ktk * 4240 + bIdx[lp] + 4 * c] = f2tf32(bv[c]);
            }
        }
        __syncthreads();

        float accs[4][4][4];
        #pragma unroll
        for (int i = 0; i < 4; i++)
            #pragma unroll
            for (int j = 0; j < 4; j++)
                #pragma unroll
                for (int r = 0; r < 4; r++) accs[i][j][r] = 0.f;

        #pragma unroll
        for (int ktile = 0; ktile < 2; ktile++) {
            uint4 bf[2][4];
            #pragma unroll
            for (int kp = 0; kp < 2; kp++)
                #pragma unroll
                for (int j = 0; j < 4; j++)
                    bf[kp][j] = *reinterpret_cast<const uint4*>(
                        &KVB[ktile * 4240 + kp * 2120 + (warpN * 4 + j) * 132 + lane * 4]);
            #pragma unroll
            for (int ks = 0; ks < 4; ks++) {
                uint4 af[4];
                #pragma unroll
                for (int i = 0; i < 4; i++)
                    af[i] = *reinterpret_cast<const uint4*>(
                        &QA[ktile * 4112 + ks * 1028 + (warpM * 4 + i) * 128 + lane * 4]);
                const int kp = ks >> 1, odd = ks & 1;
                #pragma unroll
                for (int i = 0; i < 4; i++)
                    #pragma unroll
                    for (int j = 0; j < 4; j++) {
                        uint32_t b0 = odd ? bf[kp][j].z : bf[kp][j].x;
                        uint32_t b1 = odd ? bf[kp][j].w : bf[kp][j].y;
                        mma8(accs[i][j], af[i], b0, b1);
                    }
            }
        }

        #pragma unroll
        for (int i = 0; i < 4; i++) {
            int row0 = bm + warpM * 64 + i * 16 + gid;
            #pragma unroll
            for (int j = 0; j < 4; j++) {
                int col = kbase + warpN * 32 + j * 8 + tig * 2;
                int2 m0 = *reinterpret_cast<const int2*>(&mask[((size_t)b * SEQ + row0) * SEQ + col]);
                int2 m1 = *reinterpret_cast<const int2*>(&mask[((size_t)b * SEQ + row0 + 8) * SEQ + col]);
                accs[i][j][0] = m0.x ? accs[i][j][0] * 0.125f : -0.01f;
                accs[i][j][1] = m0.y ? accs[i][j][1] * 0.125f : -0.01f;
                accs[i][j][2] = m1.x ? accs[i][j][2] * 0.125f : -0.01f;
                accs[i][j][3] = m1.y ? accs[i][j][3] * 0.125f : -0.01f;
            }
        }

        #pragma unroll
        for (int i = 0; i < 4; i++) {
            #pragma unroll
            for (int h2 = 0; h2 < 2; h2++) {
                float mx = -3e38f;
                #pragma unroll
                for (int j = 0; j < 4; j++)
                    mx = fmaxf(mx, fmaxf(accs[i][j][h2 * 2], accs[i][j][h2 * 2 + 1]));
                mx = fmaxf(mx, __shfl_xor_sync(0xffffffffu, mx, 1));
                mx = fmaxf(mx, __shfl_xor_sync(0xffffffffu, mx, 2));
                if (tig == 0)
                    RM[(warpM * 64 + i * 16 + gid + 8 * h2) * 4 + warpN] = mx;
            }
        }
        __syncthreads();

        float scl[4][2];
        #pragma unroll
        for (int i = 0; i < 4; i++) {
            #pragma unroll
            for (int h2 = 0; h2 < 2; h2++) {
                int rowl = warpM * 64 + i * 16 + gid + 8 * h2;
                float tm = fmaxf(fmaxf(RM[rowl * 4 + 0], RM[rowl * 4 + 1]),
                                 fmaxf(RM[rowl * 4 + 2], RM[rowl * 4 + 3]));
                float mn = fmaxf(m_run[i][h2], tm);
                scl[i][h2] = __expf(m_run[i][h2] - mn);
                m_run[i][h2] = mn;
                l_run[i][h2] *= scl[i][h2];
            }
        }
        #pragma unroll
        for (int i = 0; i < 4; i++)
            #pragma unroll
            for (int j = 0; j < 2; j++) {
                acc_o[i][j][0] *= scl[i][0];
                acc_o[i][j][1] *= scl[i][0];
                acc_o[i][j][2] *= scl[i][1];
                acc_o[i][j][3] *= scl[i][1];
            }

        float tsum[4][2];
        #pragma unroll
        for (int i = 0; i < 4; i++) { tsum[i][0] = 0.f; tsum[i][1] = 0.f; }

        #pragma unroll
        for (int i = 0; i < 4; i++) {
            #pragma unroll
            for (int j = 0; j < 4; j++) {
                #pragma unroll
                for (int r = 0; r < 4; r++) {
                    const int h2 = r >> 1;
                    float p = __expf(accs[i][j][r] - m_run[i][h2]);
                    accs[i][j][r] = p;
                    tsum[i][h2] += p;
                    int word = warpN * 4112 + j * 1028 + (warpM * 4 + i) * 128 + gid * 16
                             + h2 + 2 * (tig >> 1) + 4 * ((2 * tig + (r & 1)) & 3);
                    PA[word] = f2tf32(p);
                }
            }
        }
        #pragma unroll
        for (int i = 0; i < 4; i++) {
            #pragma unroll
            for (int h2 = 0; h2 < 2; h2++) {
                float sv = tsum[i][h2];
                sv += __shfl_xor_sync(0xffffffffu, sv, 1);
                sv += __shfl_xor_sync(0xffffffffu, sv, 2);
                if (tig == 0)
                    RS[(warpM * 64 + i * 16 + gid + 8 * h2) * 4 + warpN] = sv;
            }
        }

        #pragma unroll
        for (int ktv = 0; ktv < 4; ktv++) {
            #pragma unroll
            for (int lp = 0; lp < 2; lp++) {
                int r = rbase + (lp << 5);
                float4 f = *reinterpret_cast<const float4*>(
                    vptr + (size_t)r * SEQ + kbase + ktv * 32 + chunk * 4);
                float bv[4] = {f.x, f.y, f.z, f.w};
                #pragma unroll
                for (int c = 0; c < 4; c++)
                    KVB[ktv * 2128 + bIdx64[lp] + 4 * c] = f2tf32(bv[c]);
            }
        }
        __syncthreads();

        #pragma unroll
        for (int i = 0; i < 4; i++) {
            #pragma unroll
            for (int h2 = 0; h2 < 2; h2++) {
                int rowl = warpM * 64 + i * 16 + gid + 8 * h2;
                l_run[i][h2] += RS[rowl * 4 + 0] + RS[rowl * 4 + 1]
                              + RS[rowl * 4 + 2] + RS[rowl * 4 + 3];
            }
        }

        #pragma unroll
        for (int ktv = 0; ktv < 4; ktv++) {
            uint4 bf[2][2];
            #pragma unroll
            for (int kp = 0; kp < 2; kp++)
                #pragma unroll
                for (int j = 0; j < 2; j++)
                    bf[kp][j] = *reinterpret_cast<const uint4*>(
                        &KVB[ktv * 2128 + kp * 1064 + (warpN * 2 + j) * 132 + lane * 4]);
            #pragma unroll
            for (int ks = 0; ks < 4; ks++) {
                uint4 af[4];
                #pragma unroll
                for (int i = 0; i < 4; i++)
                    af[i] = *reinterpret_cast<const uint4*>(
                        &PA[ktv * 4112 + ks * 1028 + (warpM * 4 + i) * 128 + lane * 4]);
                const int kp = ks >> 1, odd = ks & 1;
                #pragma unroll
                for (int i = 0; i < 4; i++)
                    #pragma unroll
                    for (int j = 0; j < 2; j++) {
                        uint32_t b0 = odd ? bf[kp][j].z : bf[kp][j].x;
                        uint32_t b1 = odd ? bf[kp][j].w : bf[kp][j].y;
                        mma8(acc_o[i][j], af[i], b0, b1);
                    }
            }
        }
        __syncthreads();
    }

    #pragma unroll
    for (int i = 0; i < 4; i++) {
        int row0 = bm + warpM * 64 + i * 16 + gid;
        float inv0 = 1.0f / l_run[i][0];
        float inv1 = 1.0f / l_run[i][1];
        #pragma unroll
        for (int j = 0; j < 2; j++) {
            int col = warpN * 16 + j * 8 + tig * 2;
            *reinterpret_cast<float2*>(o + ((size_t)(b * SEQ + row0)) * EMB + h * HD + col) =
                make_float2(acc_o[i][j][0] * inv0, acc_o[i][j][1] * inv0);
            *reinterpret_cast<float2*>(o + ((size_t)(b * SEQ + row0 + 8)) * EMB + h * HD + col) =
                make_float2(acc_o[i][j][2] * inv1, acc_o[i][j][3] * inv1);
        }
    }
}

// ---------------- launch ----------------
extern "C" void kernel_launch(void* const* d_in, const int* in_sizes, int n_in,
                              void* d_out, int out_size)
{
    const float* x   = (const float*)d_in[0];
    const int*   mask= (const int*)  d_in[1];
    const float* Wq  = (const float*)d_in[2];
    const float* bq  = (const float*)d_in[3];
    const float* Wk  = (const float*)d_in[4];
    const float* bk  = (const float*)d_in[5];
    const float* Wv  = (const float*)d_in[6];
    const float* bv  = (const float*)d_in[7];
    const float* Wo  = (const float*)d_in[8];
    const float* bo  = (const float*)d_in[9];
    const float* W1  = (const float*)d_in[10];
    const float* b1  = (const float*)d_in[11];
    const float* W2  = (const float*)d_in[12];
    const float* b2  = (const float*)d_in[13];
    const float* g1  = (const float*)d_in[14];
    const float* be1 = (const float*)d_in[15];
    const float* g2  = (const float*)d_in[16];
    const float* be2 = (const float*)d_in[17];
    float* out = (float*)d_out;

    float *nx, *q, *k, *v, *vt, *o, *x1, *nx2, *hbuf;
    cudaGetSymbolAddress((void**)&nx,   g_nx);
    cudaGetSymbolAddress((void**)&q,    g_q);
    cudaGetSymbolAddress((void**)&k,    g_k);
    cudaGetSymbolAddress((void**)&v,    g_v);
    cudaGetSymbolAddress((void**)&vt,   g_vt);
    cudaGetSymbolAddress((void**)&o,    g_o);
    cudaGetSymbolAddress((void**)&x1,   g_x1);
    cudaGetSymbolAddress((void**)&nx2,  g_nx2);
    cudaGetSymbolAddress((void**)&hbuf, g_h);

    cudaFuncSetAttribute(flash_attn, cudaFuncAttributeMaxDynamicSharedMemorySize, FA_SMEM_BYTES);

    const dim3 gEE(EMB / 128, MROWS / 128);
    const dim3 gFF(DFF / 128, MROWS / 128);

    layernorm_k<<<MROWS, 256>>>(x, g1, be1, nx);
    gemm_qkv<<<dim3(EMB / 128, MROWS / 128, 3), 256>>>(nx, Wq, Wk, Wv, bq, bk, bv, q, k, v);

    transpose_v_k<<<dim3(SEQ / 32, HD / 32, BB * NH), 256>>>(v, vt);
    flash_attn<<<dim3(SEQ / 128, BB * NH), 256, FA_SMEM_BYTES>>>(q, k, vt, mask, o);

    gemm_tc<0><<<gEE, 256>>>(o, Wo, bo, x, x1, MROWS, EMB, EMB);
    layernorm_k<<<MROWS, 256>>>(x1, g2, be2, nx2);
    gemm_tc<1><<<gFF, 256>>>(nx2, W1, b1, nullptr, hbuf, MROWS, DFF, EMB);
    gemm_tc<0><<<gEE, 256>>>(hbuf, W2, b2, x1, out, MROWS, EMB, DFF);
}

// round 13
// speedup vs baseline: 1.2177x; 1.0238x over previous
#include <cuda_runtime.h>
#include <math.h>
#include <stdint.h>

#define BB   4
#define SEQ  1024
#define EMB  1024
#define NH   16
#define HD   64
#define DFF  4096
#define MROWS (BB*SEQ)   // 4096

// ---------------- scratch (static device globals; no allocation) ----------------
__device__ float g_nx [MROWS*EMB];
__device__ float g_q  [MROWS*EMB];
__device__ float g_k  [MROWS*EMB];
__device__ float g_v  [MROWS*EMB];
__device__ float g_vt [BB*NH*HD*SEQ];   // V transposed per head: [bh][d][seq]
__device__ float g_o  [MROWS*EMB];
__device__ float g_x1 [MROWS*EMB];
__device__ float g_nx2[MROWS*EMB];
__device__ float g_h  [MROWS*DFF];

// ---------------- helpers ----------------
__device__ __forceinline__ uint32_t f2tf32(float f) {
    uint32_t u;
    asm("cvt.rna.tf32.f32 %0, %1;" : "=r"(u) : "f"(f));
    return u;
}

__device__ __forceinline__ void mma8(float c[4], const uint4& a, uint32_t b0, uint32_t b1) {
    asm volatile(
        "mma.sync.aligned.m16n8k8.row.col.f32.tf32.tf32.f32 "
        "{%0,%1,%2,%3},{%4,%5,%6,%7},{%8,%9},{%0,%1,%2,%3};"
        : "+f"(c[0]), "+f"(c[1]), "+f"(c[2]), "+f"(c[3])
        : "r"(a.x), "r"(a.y), "r"(a.z), "r"(a.w), "r"(b0), "r"(b1));
}

__device__ __forceinline__ float gelu_f(float x) {
    const float c = 0.7978845608028654f;  // sqrt(2/pi)
    float t = tanhf(c * (x + 0.044715f * x * x * x));
    return 0.5f * x * (1.0f + t);
}

// Frag-order staging layouts (conflict-free; bank-verified in R4):
// A128 (128 rows, 32 k): word = kstep*1028 + m16*128 + (m&7)*16 + ((m>>3)&1) + 2*k4 + 4*c
// A64  ( 64 rows, 32 k): word = kstep*516  + m16*128 + ...   (m16 = row>>4, 4 blocks)
// B128 (128 rows, 32 k): word = kpair*2120 + n8*132 + (n&7)*16 + 2*(kstep&1) + k4 + 4*c
// B64  ( 64 rows, 32 k): kpair stride 1064
#define A_WORDS 4112
#define B_WORDS_128 4240
#define B_WORDS_64  2128

// ---------------- LayerNorm (one block per row of 1024) ----------------
__global__ __launch_bounds__(256)
void layernorm_k(const float* __restrict__ x, const float* __restrict__ g,
                 const float* __restrict__ b, float* __restrict__ out)
{
    __shared__ float red[8];
    const int row = blockIdx.x;
    const int tid = threadIdx.x;
    const float* xr = x + (size_t)row * EMB;

    float4 f = reinterpret_cast<const float4*>(xr)[tid];

    float s = f.x + f.y + f.z + f.w;
    #pragma unroll
    for (int o = 16; o > 0; o >>= 1) s += __shfl_xor_sync(0xffffffffu, s, o);
    if ((tid & 31) == 0) red[tid >> 5] = s;
    __syncthreads();
    float mean = 0.f;
    #pragma unroll
    for (int i = 0; i < 8; i++) mean += red[i];
    mean *= (1.0f / (float)EMB);
    __syncthreads();

    float dx0 = f.x - mean, dx1 = f.y - mean, dx2 = f.z - mean, dx3 = f.w - mean;
    float ss = dx0*dx0 + dx1*dx1 + dx2*dx2 + dx3*dx3;
    #pragma unroll
    for (int o = 16; o > 0; o >>= 1) ss += __shfl_xor_sync(0xffffffffu, ss, o);
    if ((tid & 31) == 0) red[tid >> 5] = ss;
    __syncthreads();
    float var = 0.f;
    #pragma unroll
    for (int i = 0; i < 8; i++) var += red[i];
    var *= (1.0f / (float)(EMB - 1));
    const float rs = 1.0f / (sqrtf(var) + 1e-8f);

    const float4 gg = reinterpret_cast<const float4*>(g)[tid];
    const float4 bb = reinterpret_cast<const float4*>(b)[tid];
    float4 r;
    r.x = gg.x * dx0 * rs + bb.x;
    r.y = gg.y * dx1 * rs + bb.y;
    r.z = gg.z * dx2 * rs + bb.z;
    r.w = gg.w * dx3 * rs + bb.w;
    reinterpret_cast<float4*>(out + (size_t)row * EMB)[tid] = r;
}

// ================= tf32 mma.sync GEMM body (R11) =================
template <int EPI>   // 0 = none, 1 = gelu
__device__ __forceinline__
void gemm_body(const float* __restrict__ A, const float* __restrict__ W,
               const float* __restrict__ bias, const float* __restrict__ res,
               float* __restrict__ C, int M, int N, int K)
{
    __shared__ uint32_t Aw[A_WORDS];
    __shared__ uint32_t Bw[B_WORDS_128];

    const int tid = threadIdx.x;
    const int lane = tid & 31;
    const int wid = tid >> 5;
    const int warpM = wid >> 2, warpN = wid & 3;
    const int bm = blockIdx.y * 128;
    const int bn = blockIdx.x * 128;

    const int chunk = lane & 7;
    const int kstep = chunk >> 1;
    const int k4 = chunk & 1;
    const int kpair = kstep >> 1;
    const int rbase = (((lane >> 3) & 1)) | ((wid & 3) << 1) | (((lane >> 4) & 1) << 3) | ((wid >> 2) << 4);

    int aIdx[4], bIdx[4];
    #pragma unroll
    for (int lp = 0; lp < 4; lp++) {
        int r = rbase + (lp << 5);
        aIdx[lp] = kstep * 1028 + (r >> 4) * 128 + (r & 7) * 16 + ((r >> 3) & 1) + 2 * k4;
        bIdx[lp] = kpair * 2120 + (r >> 3) * 132 + (r & 7) * 16 + 2 * (kstep & 1) + k4;
    }

    float acc[4][4][4];
    #pragma unroll
    for (int i = 0; i < 4; i++)
        #pragma unroll
        for (int j = 0; j < 4; j++)
            #pragma unroll
            for (int r = 0; r < 4; r++) acc[i][j][r] = 0.f;

    const int nk = K >> 5;

    for (int kt = 0; kt < nk; kt++) {
        const int k0 = kt << 5;
        __syncthreads();
        #pragma unroll
        for (int lp = 0; lp < 4; lp++) {
            int r = rbase + (lp << 5);
            float4 fa = *reinterpret_cast<const float4*>(A + (size_t)(bm + r) * K + k0 + chunk * 4);
            float4 fw = *reinterpret_cast<const float4*>(W + (size_t)(bn + r) * K + k0 + chunk * 4);
            float av[4] = {fa.x, fa.y, fa.z, fa.w};
            float bv[4] = {fw.x, fw.y, fw.z, fw.w};
            #pragma unroll
            for (int c = 0; c < 4; c++) {
                Aw[aIdx[lp] + 4 * c] = f2tf32(av[c]);
                Bw[bIdx[lp] + 4 * c] = f2tf32(bv[c]);
            }
        }
        __syncthreads();

        uint4 bf[4];
        #pragma unroll
        for (int ks = 0; ks < 4; ks++) {
            const int kp = ks >> 1, odd = ks & 1;
            if (!odd) {
                #pragma unroll
                for (int j = 0; j < 4; j++)
                    bf[j] = *reinterpret_cast<const uint4*>(&Bw[kp * 2120 + (warpN * 4 + j) * 132 + lane * 4]);
            }
            uint4 af[4];
            #pragma unroll
            for (int i = 0; i < 4; i++)
                af[i] = *reinterpret_cast<const uint4*>(&Aw[ks * 1028 + (warpM * 4 + i) * 128 + lane * 4]);
            #pragma unroll
            for (int i = 0; i < 4; i++)
                #pragma unroll
                for (int j = 0; j < 4; j++) {
                    uint32_t b0 = odd ? bf[j].z : bf[j].x;
                    uint32_t b1 = odd ? bf[j].w : bf[j].y;
                    mma8(acc[i][j], af[i], b0, b1);
                }
        }
    }

    const int gid = lane >> 2, tig = lane & 3;
    #pragma unroll
    for (int i = 0; i < 4; i++) {
        int row0 = bm + warpM * 64 + i * 16 + gid;
        #pragma unroll
        for (int j = 0; j < 4; j++) {
            int col = bn + warpN * 32 + j * 8 + tig * 2;
            float b0 = bias[col], b1 = bias[col + 1];
            float v0 = acc[i][j][0] + b0;
            float v1 = acc[i][j][1] + b1;
            float v2 = acc[i][j][2] + b0;
            float v3 = acc[i][j][3] + b1;
            if (EPI == 1) { v0 = gelu_f(v0); v1 = gelu_f(v1); v2 = gelu_f(v2); v3 = gelu_f(v3); }
            if (res) {
                v0 += res[(size_t)row0 * N + col];
                v1 += res[(size_t)row0 * N + col + 1];
                v2 += res[(size_t)(row0 + 8) * N + col];
                v3 += res[(size_t)(row0 + 8) * N + col + 1];
            }
            *reinterpret_cast<float2*>(C + (size_t)row0 * N + col)       = make_float2(v0, v1);
            *reinterpret_cast<float2*>(C + (size_t)(row0 + 8) * N + col) = make_float2(v2, v3);
        }
    }
}

template <int EPI>
__global__ __launch_bounds__(256, 2)
void gemm_tc(const float* __restrict__ A, const float* __restrict__ W,
             const float* __restrict__ bias, const float* __restrict__ res,
             float* __restrict__ C, int M, int N, int K)
{
    gemm_body<EPI>(A, W, bias, res, C, M, N, K);
}

__global__ __launch_bounds__(256, 2)
void gemm_qkv(const float* __restrict__ A,
              const float* __restrict__ Wq, const float* __restrict__ Wk, const float* __restrict__ Wv,
              const float* __restrict__ bq, const float* __restrict__ bk, const float* __restrict__ bv,
              float* __restrict__ q, float* __restrict__ k, float* __restrict__ v)
{
    const int z = blockIdx.z;
    const float* W = (z == 0) ? Wq : (z == 1) ? Wk : Wv;
    const float* bias = (z == 0) ? bq : (z == 1) ? bk : bv;
    float* C = (z == 0) ? q : (z == 1) ? k : v;
    gemm_body<0>(A, W, bias, nullptr, C, MROWS, EMB, EMB);
}

// ================= V transpose per head: vt[bh][d][s] = v[b][s][h*64+d] =================
__global__ __launch_bounds__(256)
void transpose_v_k(const float* __restrict__ v, float* __restrict__ vt)
{
    __shared__ float t[32][33];
    const int bh = blockIdx.z;
    const int b = bh >> 4, h = bh & 15;
    const int s0 = blockIdx.x * 32;
    const int d0 = blockIdx.y * 32;
    const int x = threadIdx.x & 31;
    const int y0 = threadIdx.x >> 5;

    #pragma unroll
    for (int j = 0; j < 4; j++) {
        int sr = y0 + j * 8;
        t[sr][x] = v[((size_t)(b * SEQ + s0 + sr)) * EMB + h * HD + d0 + x];
    }
    __syncthreads();
    #pragma unroll
    for (int j = 0; j < 4; j++) {
        int dr = y0 + j * 8;
        vt[((size_t)bh * HD + d0 + dr) * SEQ + s0 + x] = t[x][dr];
    }
}

// ================= Fused flash attention, 64-row q tiles, 2 CTAs/SM =================
// smem (words): QA [0,4128) 2 ktiles x 2064 (A64 layout)
//               KVB[4128,12640) K: 2 x 4240 | V: 4 x 2128
//               PA [12640,20896) 4 ktiles x 2064 (A64 layout)
//               RM [20896,21152) 64 x 4, RS [21152,21408)
#define FA_QA   0
#define FA_KVB  4128
#define FA_PA   12640
#define FA_RM   20896
#define FA_RS   21152
#define FA_SMEM_BYTES (21408 * 4)   // 85632 B -> 2 CTAs/SM

__global__ __launch_bounds__(256, 2)
void flash_attn(const float* __restrict__ q, const float* __restrict__ kk,
                const float* __restrict__ vt, const int* __restrict__ mask,
                float* __restrict__ o)
{
    extern __shared__ uint32_t dyn[];
    uint32_t* QA  = dyn + FA_QA;
    uint32_t* KVB = dyn + FA_KVB;
    uint32_t* PA  = dyn + FA_PA;
    float*    RM  = reinterpret_cast<float*>(dyn + FA_RM);
    float*    RS  = reinterpret_cast<float*>(dyn + FA_RS);

    const int tid = threadIdx.x;
    const int lane = tid & 31;
    const int wid = tid >> 5;
    const int warpM = wid >> 2, warpN = wid & 3;   // 2M x 4N; warp covers 32 q rows
    const int gid = lane >> 2, tig = lane & 3;
    const int bh = blockIdx.y;
    const int b = bh >> 4, h = bh & 15;
    const int bm = blockIdx.x * 64;

    const int chunk = lane & 7;
    const int kstep = chunk >> 1;
    const int k4 = chunk & 1;
    const int kpair = kstep >> 1;
    const int rbase = (((lane >> 3) & 1)) | ((wid & 3) << 1) | (((lane >> 4) & 1) << 3) | ((wid >> 2) << 4);

    // staging indices
    int aIdx64[2];   // A64: q rows 0..63
    #pragma unroll
    for (int lp = 0; lp < 2; lp++) {
        int r = rbase + (lp << 5);
        aIdx64[lp] = kstep * 516 + (r >> 4) * 128 + (r & 7) * 16 + ((r >> 3) & 1) + 2 * k4;
    }
    int bIdx[4];     // B128: kv rows 0..127
    #pragma unroll
    for (int lp = 0; lp < 4; lp++) {
        int r = rbase + (lp << 5);
        bIdx[lp] = kpair * 2120 + (r >> 3) * 132 + (r & 7) * 16 + 2 * (kstep & 1) + k4;
    }
    int bIdx64[2];   // B64: d rows 0..63
    #pragma unroll
    for (int lp = 0; lp < 2; lp++) {
        int r = rbase + (lp << 5);
        bIdx64[lp] = kpair * 1064 + (r >> 3) * 132 + (r & 7) * 16 + 2 * (kstep & 1) + k4;
    }

    const float* qptr = q  + (size_t)(b * SEQ + bm) * EMB + h * HD;
    const float* kptr = kk + (size_t)(b * SEQ) * EMB + h * HD;
    const float* vptr = vt + (size_t)bh * HD * SEQ;

    // stage Q once (64 rows, 2 k-tiles of 32)
    #pragma unroll
    for (int ktq = 0; ktq < 2; ktq++) {
        #pragma unroll
        for (int lp = 0; lp < 2; lp++) {
            int r = rbase + (lp << 5);
            float4 f = *reinterpret_cast<const float4*>(qptr + (size_t)r * EMB + ktq * 32 + chunk * 4);
            float av[4] = {f.x, f.y, f.z, f.w};
            #pragma unroll
            for (int c = 0; c < 4; c++)
                QA[ktq * 2064 + aIdx64[lp] + 4 * c] = f2tf32(av[c]);
        }
    }

    float m_run[2][2], l_run[2][2];
    float acc_o[2][2][4];
    #pragma unroll
    for (int i = 0; i < 2; i++)
        #pragma unroll
        for (int h2 = 0; h2 < 2; h2++) { m_run[i][h2] = -3e38f; l_run[i][h2] = 0.f; }
    #pragma unroll
    for (int i = 0; i < 2; i++)
        #pragma unroll
        for (int j = 0; j < 2; j++)
            #pragma unroll
            for (int r = 0; r < 4; r++) acc_o[i][j][r] = 0.f;

    for (int kt = 0; kt < SEQ / 128; kt++) {
        const int kbase = kt * 128;

        // stage K tile (128 kv rows x 64 d)
        #pragma unroll
        for (int ktk = 0; ktk < 2; ktk++) {
            #pragma unroll
            for (int lp = 0; lp < 4; lp++) {
                int r = rbase + (lp << 5);
                float4 f = *reinterpret_cast<const float4*>(
                    kptr + (size_t)(kbase + r) * EMB + ktk * 32 + chunk * 4);
                float bv[4] = {f.x, f.y, f.z, f.w};
                #pragma unroll
                for (int c = 0; c < 4; c++)
                    KVB[ktk * 4240 + bIdx[lp] + 4 * c] = f2tf32(bv[c]);
            }
        }
        __syncthreads();

        // S = Q K^T  (64 x 128)
        float accs[2][4][4];
        #pragma unroll
        for (int i = 0; i < 2; i++)
            #pragma unroll
            for (int j = 0; j < 4; j++)
                #pragma unroll
                for (int r = 0; r < 4; r++) accs[i][j][r] = 0.f;

        #pragma unroll
        for (int ktile = 0; ktile < 2; ktile++) {
            uint4 bf[4];
            #pragma unroll
            for (int ks = 0; ks < 4; ks++) {
                const int kp = ks >> 1, odd = ks & 1;
                if (!odd) {
                    #pragma unroll
                    for (int j = 0; j < 4; j++)
                        bf[j] = *reinterpret_cast<const uint4*>(
                            &KVB[ktile * 4240 + kp * 2120 + (warpN * 4 + j) * 132 + lane * 4]);
                }
                uint4 af[2];
                #pragma unroll
                for (int i = 0; i < 2; i++)
                    af[i] = *reinterpret_cast<const uint4*>(
                        &QA[ktile * 2064 + ks * 516 + (warpM * 2 + i) * 128 + lane * 4]);
                #pragma unroll
                for (int i = 0; i < 2; i++)
                    #pragma unroll
                    for (int j = 0; j < 4; j++) {
                        uint32_t b0 = odd ? bf[j].z : bf[j].x;
                        uint32_t b1 = odd ? bf[j].w : bf[j].y;
                        mma8(accs[i][j], af[i], b0, b1);
                    }
            }
        }

        // mask + scale
        #pragma unroll
        for (int i = 0; i < 2; i++) {
            int row0 = bm + warpM * 32 + i * 16 + gid;
            #pragma unroll
            for (int j = 0; j < 4; j++) {
                int col = kbase + warpN * 32 + j * 8 + tig * 2;
                int2 m0 = *reinterpret_cast<const int2*>(&mask[((size_t)b * SEQ + row0) * SEQ + col]);
                int2 m1 = *reinterpret_cast<const int2*>(&mask[((size_t)b * SEQ + row0 + 8) * SEQ + col]);
                accs[i][j][0] = m0.x ? accs[i][j][0] * 0.125f : -0.01f;
                accs[i][j][1] = m0.y ? accs[i][j][1] * 0.125f : -0.01f;
                accs[i][j][2] = m1.x ? accs[i][j][2] * 0.125f : -0.01f;
                accs[i][j][3] = m1.y ? accs[i][j][3] * 0.125f : -0.01f;
            }
        }

        // tile row max -> RM
        #pragma unroll
        for (int i = 0; i < 2; i++) {
            #pragma unroll
            for (int h2 = 0; h2 < 2; h2++) {
                float mx = -3e38f;
                #pragma unroll
                for (int j = 0; j < 4; j++)
                    mx = fmaxf(mx, fmaxf(accs[i][j][h2 * 2], accs[i][j][h2 * 2 + 1]));
                mx = fmaxf(mx, __shfl_xor_sync(0xffffffffu, mx, 1));
                mx = fmaxf(mx, __shfl_xor_sync(0xffffffffu, mx, 2));
                if (tig == 0)
                    RM[(warpM * 32 + i * 16 + gid + 8 * h2) * 4 + warpN] = mx;
            }
        }
        __syncthreads();

        // combine with running stats; rescale O
        float scl[2][2];
        #pragma unroll
        for (int i = 0; i < 2; i++) {
            #pragma unroll
            for (int h2 = 0; h2 < 2; h2++) {
                int rowl = warpM * 32 + i * 16 + gid + 8 * h2;
                float tm = fmaxf(fmaxf(RM[rowl * 4 + 0], RM[rowl * 4 + 1]),
                                 fmaxf(RM[rowl * 4 + 2], RM[rowl * 4 + 3]));
                float mn = fmaxf(m_run[i][h2], tm);
                scl[i][h2] = __expf(m_run[i][h2] - mn);
                m_run[i][h2] = mn;
                l_run[i][h2] *= scl[i][h2];
            }
        }
        #pragma unroll
        for (int i = 0; i < 2; i++)
            #pragma unroll
            for (int j = 0; j < 2; j++) {
                acc_o[i][j][0] *= scl[i][0];
                acc_o[i][j][1] *= scl[i][0];
                acc_o[i][j][2] *= scl[i][1];
                acc_o[i][j][3] *= scl[i][1];
            }

        // p = exp(s - m); partial sums; scatter P into PA (A64 layout)
        float tsum[2][2];
        #pragma unroll
        for (int i = 0; i < 2; i++) { tsum[i][0] = 0.f; tsum[i][1] = 0.f; }

        #pragma unroll
        for (int i = 0; i < 2; i++) {
            #pragma unroll
            for (int j = 0; j < 4; j++) {
                #pragma unroll
                for (int r = 0; r < 4; r++) {
                    const int h2 = r >> 1;
                    float p = __expf(accs[i][j][r] - m_run[i][h2]);
                    tsum[i][h2] += p;
                    int word = warpN * 2064 + j * 516 + (warpM * 2 + i) * 128 + gid * 16
                             + h2 + 2 * (tig >> 1) + 4 * ((2 * tig + (r & 1)) & 3);
                    PA[word] = f2tf32(p);
                }
            }
        }
        #pragma unroll
        for (int i = 0; i < 2; i++) {
            #pragma unroll
            for (int h2 = 0; h2 < 2; h2++) {
                float sv = tsum[i][h2];
                sv += __shfl_xor_sync(0xffffffffu, sv, 1);
                sv += __shfl_xor_sync(0xffffffffu, sv, 2);
                if (tig == 0)
                    RS[(warpM * 32 + i * 16 + gid + 8 * h2) * 4 + warpN] = sv;
            }
        }

        // stage V tile into KVB (K data dead after the post-mma sync)
        #pragma unroll
        for (int ktv = 0; ktv < 4; ktv++) {
            #pragma unroll
            for (int lp = 0; lp < 2; lp++) {
                int r = rbase + (lp << 5);   // d row 0..63
                float4 f = *reinterpret_cast<const float4*>(
                    vptr + (size_t)r * SEQ + kbase + ktv * 32 + chunk * 4);
                float bv[4] = {f.x, f.y, f.z, f.w};
                #pragma unroll
                for (int c = 0; c < 4; c++)
                    KVB[ktv * 2128 + bIdx64[lp] + 4 * c] = f2tf32(bv[c]);
            }
        }
        __syncthreads();

        // l update
        #pragma unroll
        for (int i = 0; i < 2; i++) {
            #pragma unroll
            for (int h2 = 0; h2 < 2; h2++) {
                int rowl = warpM * 32 + i * 16 + gid + 8 * h2;
                l_run[i][h2] += RS[rowl * 4 + 0] + RS[rowl * 4 + 1]
                              + RS[rowl * 4 + 2] + RS[rowl * 4 + 3];
            }
        }

        // O += P V
        #pragma unroll
        for (int ktv = 0; ktv < 4; ktv++) {
            uint4 bf[2][2];
            #pragma unroll
            for (int kp = 0; kp < 2; kp++)
                #pragma unroll
                for (int j = 0; j < 2; j++)
                    bf[kp][j] = *reinterpret_cast<const uint4*>(
                        &KVB[ktv * 2128 + kp * 1064 + (warpN * 2 + j) * 132 + lane * 4]);
            #pragma unroll
            for (int ks = 0; ks < 4; ks++) {
                uint4 af[2];
                #pragma unroll
                for (int i = 0; i < 2; i++)
                    af[i] = *reinterpret_cast<const uint4*>(
                        &PA[ktv * 2064 + ks * 516 + (warpM * 2 + i) * 128 + lane * 4]);
                const int kp = ks >> 1, odd = ks & 1;
                #pragma unroll
                for (int i = 0; i < 2; i++)
                    #pragma unroll
                    for (int j = 0; j < 2; j++) {
                        uint32_t b0 = odd ? bf[kp][j].z : bf[kp][j].x;
                        uint32_t b1 = odd ? bf[kp][j].w : bf[kp][j].y;
                        mma8(acc_o[i][j], af[i], b0, b1);
                    }
            }
        }
        __syncthreads();   // protect KVB/PA reuse next iteration
    }

    // epilogue: O / l
    #pragma unroll
    for (int i = 0; i < 2; i++) {
        int row0 = bm + warpM * 32 + i * 16 + gid;
        float inv0 = 1.0f / l_run[i][0];
        float inv1 = 1.0f / l_run[i][1];
        #pragma unroll
        for (int j = 0; j < 2; j++) {
            int col = warpN * 16 + j * 8 + tig * 2;
            *reinterpret_cast<float2*>(o + ((size_t)(b * SEQ + row0)) * EMB + h * HD + col) =
                make_float2(acc_o[i][j][0] * inv0, acc_o[i][j][1] * inv0);
            *reinterpret_cast<float2*>(o + ((size_t)(b * SEQ + row0 + 8)) * EMB + h * HD + col) =
                make_float2(acc_o[i][j][2] * inv1, acc_o[i][j][3] * inv1);
        }
    }
}

// ---------------- launch ----------------
extern "C" void kernel_launch(void* const* d_in, const int* in_sizes, int n_in,
                              void* d_out, int out_size)
{
    const float* x   = (const float*)d_in[0];
    const int*   mask= (const int*)  d_in[1];
    const float* Wq  = (const float*)d_in[2];
    const float* bq  = (const float*)d_in[3];
    const float* Wk  = (const float*)d_in[4];
    const float* bk  = (const float*)d_in[5];
    const float* Wv  = (const float*)d_in[6];
    const float* bv  = (const float*)d_in[7];
    const float* Wo  = (const float*)d_in[8];
    const float* bo  = (const float*)d_in[9];
    const float* W1  = (const float*)d_in[10];
    const float* b1  = (const float*)d_in[11];
    const float* W2  = (const float*)d_in[12];
    const float* b2  = (const float*)d_in[13];
    const float* g1  = (const float*)d_in[14];
    const float* be1 = (const float*)d_in[15];
    const float* g2  = (const float*)d_in[16];
    const float* be2 = (const float*)d_in[17];
    float* out = (float*)d_out;

    float *nx, *q, *k, *v, *vt, *o, *x1, *nx2, *hbuf;
    cudaGetSymbolAddress((void**)&nx,   g_nx);
    cudaGetSymbolAddress((void**)&q,    g_q);
    cudaGetSymbolAddress((void**)&k,    g_k);
    cudaGetSymbolAddress((void**)&v,    g_v);
    cudaGetSymbolAddress((void**)&vt,   g_vt);
    cudaGetSymbolAddress((void**)&o,    g_o);
    cudaGetSymbolAddress((void**)&x1,   g_x1);
    cudaGetSymbolAddress((void**)&nx2,  g_nx2);
    cudaGetSymbolAddress((void**)&hbuf, g_h);

    cudaFuncSetAttribute(flash_attn, cudaFuncAttributeMaxDynamicSharedMemorySize, FA_SMEM_BYTES);

    const dim3 gEE(EMB / 128, MROWS / 128);
    const dim3 gFF(DFF / 128, MROWS / 128);

    layernorm_k<<<MROWS, 256>>>(x, g1, be1, nx);
    gemm_qkv<<<dim3(EMB / 128, MROWS / 128, 3), 256>>>(nx, Wq, Wk, Wv, bq, bk, bv, q, k, v);

    transpose_v_k<<<dim3(SEQ / 32, HD / 32, BB * NH), 256>>>(v, vt);
    flash_attn<<<dim3(SEQ / 64, BB * NH), 256, FA_SMEM_BYTES>>>(q, k, vt, mask, o);

    gemm_tc<0><<<gEE, 256>>>(o, Wo, bo, x, x1, MROWS, EMB, EMB);
    layernorm_k<<<MROWS, 256>>>(x1, g2, be2, nx2);
    gemm_tc<1><<<gFF, 256>>>(nx2, W1, b1, nullptr, hbuf, MROWS, DFF, EMB);
    gemm_tc<0><<<gEE, 256>>>(hbuf, W2, b2, x1, out, MROWS, EMB, DFF);
}

// round 15
// speedup vs baseline: 1.2310x; 1.0110x over previous
#include <cuda_runtime.h>
#include <math.h>
#include <stdint.h>

#define BB   4
#define SEQ  1024
#define EMB  1024
#define NH   16
#define HD   64
#define DFF  4096
#define MROWS (BB*SEQ)   // 4096

// ---------------- scratch (static device globals; no allocation) ----------------
__device__ float g_nx [MROWS*EMB];
__device__ float g_q  [MROWS*EMB];
__device__ float g_k  [MROWS*EMB];
__device__ float g_v  [MROWS*EMB];
__device__ float g_vt [BB*NH*HD*SEQ];   // V transposed per head: [bh][d][seq]
__device__ float g_o  [MROWS*EMB];
__device__ float g_x1 [MROWS*EMB];
__device__ float g_nx2[MROWS*EMB];
__device__ float g_h  [MROWS*DFF];

// ---------------- helpers ----------------
__device__ __forceinline__ uint32_t f2tf32(float f) {
    uint32_t u;
    asm("cvt.rna.tf32.f32 %0, %1;" : "=r"(u) : "f"(f));
    return u;
}

__device__ __forceinline__ void mma8(float c[4], const uint4& a, uint32_t b0, uint32_t b1) {
    asm volatile(
        "mma.sync.aligned.m16n8k8.row.col.f32.tf32.tf32.f32 "
        "{%0,%1,%2,%3},{%4,%5,%6,%7},{%8,%9},{%0,%1,%2,%3};"
        : "+f"(c[0]), "+f"(c[1]), "+f"(c[2]), "+f"(c[3])
        : "r"(a.x), "r"(a.y), "r"(a.z), "r"(a.w), "r"(b0), "r"(b1));
}

__device__ __forceinline__ float gelu_f(float x) {
    const float c = 0.7978845608028654f;  // sqrt(2/pi)
    float t = tanhf(c * (x + 0.044715f * x * x * x));
    return 0.5f * x * (1.0f + t);
}

// Frag-order staging layouts (conflict-free; bank-verified in R4):
// A128 (128 rows, 32 k): word = kstep*1028 + m16*128 + (m&7)*16 + ((m>>3)&1) + 2*k4 + 4*c
// A64  ( 64 rows, 32 k): word = kstep*516  + m16*128 + ...
// B128 (128 rows, 32 k): word = kpair*2120 + n8*132 + (n&7)*16 + 2*(kstep&1) + k4 + 4*c
// B64  ( 64 rows, 32 k): kpair stride 1064
#define A_WORDS 4112
#define B_WORDS_128 4240
#define B_WORDS_64  2128

// PA swizzle: applied to the low-7-bit offset within each 128-word block,
// identical on write and read: injects gid>>1 into the c bits.
#define PSWZ(w) ((w) ^ ((((w) >> 5) & 3) << 2))

// ---------------- LayerNorm (one block per row of 1024) ----------------
__global__ __launch_bounds__(256)
void layernorm_k(const float* __restrict__ x, const float* __restrict__ g,
                 const float* __restrict__ b, float* __restrict__ out)
{
    __shared__ float red[8];
    const int row = blockIdx.x;
    const int tid = threadIdx.x;
    const float* xr = x + (size_t)row * EMB;

    float4 f = reinterpret_cast<const float4*>(xr)[tid];

    float s = f.x + f.y + f.z + f.w;
    #pragma unroll
    for (int o = 16; o > 0; o >>= 1) s += __shfl_xor_sync(0xffffffffu, s, o);
    if ((tid & 31) == 0) red[tid >> 5] = s;
    __syncthreads();
    float mean = 0.f;
    #pragma unroll
    for (int i = 0; i < 8; i++) mean += red[i];
    mean *= (1.0f / (float)EMB);
    __syncthreads();

    float dx0 = f.x - mean, dx1 = f.y - mean, dx2 = f.z - mean, dx3 = f.w - mean;
    float ss = dx0*dx0 + dx1*dx1 + dx2*dx2 + dx3*dx3;
    #pragma unroll
    for (int o = 16; o > 0; o >>= 1) ss += __shfl_xor_sync(0xffffffffu, ss, o);
    if ((tid & 31) == 0) red[tid >> 5] = ss;
    __syncthreads();
    float var = 0.f;
    #pragma unroll
    for (int i = 0; i < 8; i++) var += red[i];
    var *= (1.0f / (float)(EMB - 1));
    const float rs = 1.0f / (sqrtf(var) + 1e-8f);

    const float4 gg = reinterpret_cast<const float4*>(g)[tid];
    const float4 bb = reinterpret_cast<const float4*>(b)[tid];
    float4 r;
    r.x = gg.x * dx0 * rs + bb.x;
    r.y = gg.y * dx1 * rs + bb.y;
    r.z = gg.z * dx2 * rs + bb.z;
    r.w = gg.w * dx3 * rs + bb.w;
    reinterpret_cast<float4*>(out + (size_t)row * EMB)[tid] = r;
}

// ================= tf32 mma.sync GEMM body (R11, unchanged) =================
template <int EPI>   // 0 = none, 1 = gelu
__device__ __forceinline__
void gemm_body(const float* __restrict__ A, const float* __restrict__ W,
               const float* __restrict__ bias, const float* __restrict__ res,
               float* __restrict__ C, int M, int N, int K)
{
    __shared__ uint32_t Aw[A_WORDS];
    __shared__ uint32_t Bw[B_WORDS_128];

    const int tid = threadIdx.x;
    const int lane = tid & 31;
    const int wid = tid >> 5;
    const int warpM = wid >> 2, warpN = wid & 3;
    const int bm = blockIdx.y * 128;
    const int bn = blockIdx.x * 128;

    const int chunk = lane & 7;
    const int kstep = chunk >> 1;
    const int k4 = chunk & 1;
    const int kpair = kstep >> 1;
    const int rbase = (((lane >> 3) & 1)) | ((wid & 3) << 1) | (((lane >> 4) & 1) << 3) | ((wid >> 2) << 4);

    int aIdx[4], bIdx[4];
    #pragma unroll
    for (int lp = 0; lp < 4; lp++) {
        int r = rbase + (lp << 5);
        aIdx[lp] = kstep * 1028 + (r >> 4) * 128 + (r & 7) * 16 + ((r >> 3) & 1) + 2 * k4;
        bIdx[lp] = kpair * 2120 + (r >> 3) * 132 + (r & 7) * 16 + 2 * (kstep & 1) + k4;
    }

    float acc[4][4][4];
    #pragma unroll
    for (int i = 0; i < 4; i++)
        #pragma unroll
        for (int j = 0; j < 4; j++)
            #pragma unroll
            for (int r = 0; r < 4; r++) acc[i][j][r] = 0.f;

    const int nk = K >> 5;

    for (int kt = 0; kt < nk; kt++) {
        const int k0 = kt << 5;
        __syncthreads();
        #pragma unroll
        for (int lp = 0; lp < 4; lp++) {
            int r = rbase + (lp << 5);
            float4 fa = *reinterpret_cast<const float4*>(A + (size_t)(bm + r) * K + k0 + chunk * 4);
            float4 fw = *reinterpret_cast<const float4*>(W + (size_t)(bn + r) * K + k0 + chunk * 4);
            float av[4] = {fa.x, fa.y, fa.z, fa.w};
            float bv[4] = {fw.x, fw.y, fw.z, fw.w};
            #pragma unroll
            for (int c = 0; c < 4; c++) {
                Aw[aIdx[lp] + 4 * c] = f2tf32(av[c]);
                Bw[bIdx[lp] + 4 * c] = f2tf32(bv[c]);
            }
        }
        __syncthreads();

        uint4 bf[4];
        #pragma unroll
        for (int ks = 0; ks < 4; ks++) {
            const int kp = ks >> 1, odd = ks & 1;
            if (!odd) {
                #pragma unroll
                for (int j = 0; j < 4; j++)
                    bf[j] = *reinterpret_cast<const uint4*>(&Bw[kp * 2120 + (warpN * 4 + j) * 132 + lane * 4]);
            }
            uint4 af[4];
            #pragma unroll
            for (int i = 0; i < 4; i++)
                af[i] = *reinterpret_cast<const uint4*>(&Aw[ks * 1028 + (warpM * 4 + i) * 128 + lane * 4]);
            #pragma unroll
            for (int i = 0; i < 4; i++)
                #pragma unroll
                for (int j = 0; j < 4; j++) {
                    uint32_t b0 = odd ? bf[j].z : bf[j].x;
                    uint32_t b1 = odd ? bf[j].w : bf[j].y;
                    mma8(acc[i][j], af[i], b0, b1);
                }
        }
    }

    const int gid = lane >> 2, tig = lane & 3;
    #pragma unroll
    for (int i = 0; i < 4; i++) {
        int row0 = bm + warpM * 64 + i * 16 + gid;
        #pragma unroll
        for (int j = 0; j < 4; j++) {
            int col = bn + warpN * 32 + j * 8 + tig * 2;
            float b0 = bias[col], b1 = bias[col + 1];
            float v0 = acc[i][j][0] + b0;
            float v1 = acc[i][j][1] + b1;
            float v2 = acc[i][j][2] + b0;
            float v3 = acc[i][j][3] + b1;
            if (EPI == 1) { v0 = gelu_f(v0); v1 = gelu_f(v1); v2 = gelu_f(v2); v3 = gelu_f(v3); }
            if (res) {
                v0 += res[(size_t)row0 * N + col];
                v1 += res[(size_t)row0 * N + col + 1];
                v2 += res[(size_t)(row0 + 8) * N + col];
                v3 += res[(size_t)(row0 + 8) * N + col + 1];
            }
            *reinterpret_cast<float2*>(C + (size_t)row0 * N + col)       = make_float2(v0, v1);
            *reinterpret_cast<float2*>(C + (size_t)(row0 + 8) * N + col) = make_float2(v2, v3);
        }
    }
}

template <int EPI>
__global__ __launch_bounds__(256, 2)
void gemm_tc(const float* __restrict__ A, const float* __restrict__ W,
             const float* __restrict__ bias, const float* __restrict__ res,
             float* __restrict__ C, int M, int N, int K)
{
    gemm_body<EPI>(A, W, bias, res, C, M, N, K);
}

__global__ __launch_bounds__(256, 2)
void gemm_qkv(const float* __restrict__ A,
              const float* __restrict__ Wq, const float* __restrict__ Wk, const float* __restrict__ Wv,
              const float* __restrict__ bq, const float* __restrict__ bk, const float* __restrict__ bv,
              float* __restrict__ q, float* __restrict__ k, float* __restrict__ v)
{
    const int z = blockIdx.z;
    const float* W = (z == 0) ? Wq : (z == 1) ? Wk : Wv;
    const float* bias = (z == 0) ? bq : (z == 1) ? bk : bv;
    float* C = (z == 0) ? q : (z == 1) ? k : v;
    gemm_body<0>(A, W, bias, nullptr, C, MROWS, EMB, EMB);
}

// ================= V transpose per head: vt[bh][d][s] = v[b][s][h*64+d] =================
__global__ __launch_bounds__(256)
void transpose_v_k(const float* __restrict__ v, float* __restrict__ vt)
{
    __shared__ float t[32][33];
    const int bh = blockIdx.z;
    const int b = bh >> 4, h = bh & 15;
    const int s0 = blockIdx.x * 32;
    const int d0 = blockIdx.y * 32;
    const int x = threadIdx.x & 31;
    const int y0 = threadIdx.x >> 5;

    #pragma unroll
    for (int j = 0; j < 4; j++) {
        int sr = y0 + j * 8;
        t[sr][x] = v[((size_t)(b * SEQ + s0 + sr)) * EMB + h * HD + d0 + x];
    }
    __syncthreads();
    #pragma unroll
    for (int j = 0; j < 4; j++) {
        int dr = y0 + j * 8;
        vt[((size_t)bh * HD + d0 + dr) * SEQ + s0 + x] = t[x][dr];
    }
}

// ================= Fused flash attention, 64-row q tiles, 2 CTAs/SM =================
// PA now uses the PSWZ swizzle + STS.64 paired stores (conflict-free writes).
#define FA_QA   0
#define FA_KVB  4128
#define FA_PA   12640
#define FA_RM   20896
#define FA_RS   21152
#define FA_SMEM_BYTES (21408 * 4)   // 85632 B -> 2 CTAs/SM

__global__ __launch_bounds__(256, 2)
void flash_attn(const float* __restrict__ q, const float* __restrict__ kk,
                const float* __restrict__ vt, const int* __restrict__ mask,
                float* __restrict__ o)
{
    extern __shared__ uint32_t dyn[];
    uint32_t* QA  = dyn + FA_QA;
    uint32_t* KVB = dyn + FA_KVB;
    uint32_t* PA  = dyn + FA_PA;
    float*    RM  = reinterpret_cast<float*>(dyn + FA_RM);
    float*    RS  = reinterpret_cast<float*>(dyn + FA_RS);

    const int tid = threadIdx.x;
    const int lane = tid & 31;
    const int wid = tid >> 5;
    const int warpM = wid >> 2, warpN = wid & 3;   // 2M x 4N; warp covers 32 q rows
    const int gid = lane >> 2, tig = lane & 3;
    const int bh = blockIdx.y;
    const int b = bh >> 4, h = bh & 15;
    const int bm = blockIdx.x * 64;

    const int chunk = lane & 7;
    const int kstep = chunk >> 1;
    const int k4 = chunk & 1;
    const int kpair = kstep >> 1;
    const int rbase = (((lane >> 3) & 1)) | ((wid & 3) << 1) | (((lane >> 4) & 1) << 3) | ((wid >> 2) << 4);

    int aIdx64[2];
    #pragma unroll
    for (int lp = 0; lp < 2; lp++) {
        int r = rbase + (lp << 5);
        aIdx64[lp] = kstep * 516 + (r >> 4) * 128 + (r & 7) * 16 + ((r >> 3) & 1) + 2 * k4;
    }
    int bIdx[4];
    #pragma unroll
    for (int lp = 0; lp < 4; lp++) {
        int r = rbase + (lp << 5);
        bIdx[lp] = kpair * 2120 + (r >> 3) * 132 + (r & 7) * 16 + 2 * (kstep & 1) + k4;
    }
    int bIdx64[2];
    #pragma unroll
    for (int lp = 0; lp < 2; lp++) {
        int r = rbase + (lp << 5);
        bIdx64[lp] = kpair * 1064 + (r >> 3) * 132 + (r & 7) * 16 + 2 * (kstep & 1) + k4;
    }

    // PA writer relative offsets (h2=0 words; swizzled). rlow = 0,1.
    const int pswz = ((gid >> 1) & 3) << 2;
    const int prel0 = (gid * 16 + 2 * (tig >> 1) + 4 * ((2 * tig) & 3)) ^ pswz;
    const int prel1 = (gid * 16 + 2 * (tig >> 1) + 4 * ((2 * tig + 1) & 3)) ^ pswz;
    // PA reader relative offset (swizzled)
    const int prd = (lane * 4) ^ (((lane >> 3) & 3) << 2);

    const float* qptr = q  + (size_t)(b * SEQ + bm) * EMB + h * HD;
    const float* kptr = kk + (size_t)(b * SEQ) * EMB + h * HD;
    const float* vptr = vt + (size_t)bh * HD * SEQ;

    // stage Q once
    #pragma unroll
    for (int ktq = 0; ktq < 2; ktq++) {
        #pragma unroll
        for (int lp = 0; lp < 2; lp++) {
            int r = rbase + (lp << 5);
            float4 f = *reinterpret_cast<const float4*>(qptr + (size_t)r * EMB + ktq * 32 + chunk * 4);
            float av[4] = {f.x, f.y, f.z, f.w};
            #pragma unroll
            for (int c = 0; c < 4; c++)
                QA[ktq * 2064 + aIdx64[lp] + 4 * c] = f2tf32(av[c]);
        }
    }

    float m_run[2][2], l_run[2][2];
    float acc_o[2][2][4];
    #pragma unroll
    for (int i = 0; i < 2; i++)
        #pragma unroll
        for (int h2 = 0; h2 < 2; h2++) { m_run[i][h2] = -3e38f; l_run[i][h2] = 0.f; }
    #pragma unroll
    for (int i = 0; i < 2; i++)
        #pragma unroll
        for (int j = 0; j < 2; j++)
            #pragma unroll
            for (int r = 0; r < 4; r++) acc_o[i][j][r] = 0.f;

    for (int kt = 0; kt < SEQ / 128; kt++) {
        const int kbase = kt * 128;

        // stage K tile
        #pragma unroll
        for (int ktk = 0; ktk < 2; ktk++) {
            #pragma unroll
            for (int lp = 0; lp < 4; lp++) {
                int r = rbase + (lp << 5);
                float4 f = *reinterpret_cast<const float4*>(
                    kptr + (size_t)(kbase + r) * EMB + ktk * 32 + chunk * 4);
                float bv[4] = {f.x, f.y, f.z, f.w};
                #pragma unroll
                for (int c = 0; c < 4; c++)
                    KVB[ktk * 4240 + bIdx[lp] + 4 * c] = f2tf32(bv[c]);
            }
        }
        __syncthreads();

        // S = Q K^T
        float accs[2][4][4];
        #pragma unroll
        for (int i = 0; i < 2; i++)
            #pragma unroll
            for (int j = 0; j < 4; j++)
                #pragma unroll
                for (int r = 0; r < 4; r++) accs[i][j][r] = 0.f;

        #pragma unroll
        for (int ktile = 0; ktile < 2; ktile++) {
            uint4 bf[4];
            #pragma unroll
            for (int ks = 0; ks < 4; ks++) {
                const int kp = ks >> 1, odd = ks & 1;
                if (!odd) {
                    #pragma unroll
                    for (int j = 0; j < 4; j++)
                        bf[j] = *reinterpret_cast<const uint4*>(
                            &KVB[ktile * 4240 + kp * 2120 + (warpN * 4 + j) * 132 + lane * 4]);
                }
                uint4 af[2];
                #pragma unroll
                for (int i = 0; i < 2; i++)
                    af[i] = *reinterpret_cast<const uint4*>(
                        &QA[ktile * 2064 + ks * 516 + (warpM * 2 + i) * 128 + lane * 4]);
                #pragma unroll
                for (int i = 0; i < 2; i++)
                    #pragma unroll
                    for (int j = 0; j < 4; j++) {
                        uint32_t b0 = odd ? bf[j].z : bf[j].x;
                        uint32_t b1 = odd ? bf[j].w : bf[j].y;
                        mma8(accs[i][j], af[i], b0, b1);
                    }
            }
        }

        // mask + scale
        #pragma unroll
        for (int i = 0; i < 2; i++) {
            int row0 = bm + warpM * 32 + i * 16 + gid;
            #pragma unroll
            for (int j = 0; j < 4; j++) {
                int col = kbase + warpN * 32 + j * 8 + tig * 2;
                int2 m0 = *reinterpret_cast<const int2*>(&mask[((size_t)b * SEQ + row0) * SEQ + col]);
                int2 m1 = *reinterpret_cast<const int2*>(&mask[((size_t)b * SEQ + row0 + 8) * SEQ + col]);
                accs[i][j][0] = m0.x ? accs[i][j][0] * 0.125f : -0.01f;
                accs[i][j][1] = m0.y ? accs[i][j][1] * 0.125f : -0.01f;
                accs[i][j][2] = m1.x ? accs[i][j][2] * 0.125f : -0.01f;
                accs[i][j][3] = m1.y ? accs[i][j][3] * 0.125f : -0.01f;
            }
        }

        // tile row max -> RM
        #pragma unroll
        for (int i = 0; i < 2; i++) {
            #pragma unroll
            for (int h2 = 0; h2 < 2; h2++) {
                float mx = -3e38f;
                #pragma unroll
                for (int j = 0; j < 4; j++)
                    mx = fmaxf(mx, fmaxf(accs[i][j][h2 * 2], accs[i][j][h2 * 2 + 1]));
                mx = fmaxf(mx, __shfl_xor_sync(0xffffffffu, mx, 1));
                mx = fmaxf(mx, __shfl_xor_sync(0xffffffffu, mx, 2));
                if (tig == 0)
                    RM[(warpM * 32 + i * 16 + gid + 8 * h2) * 4 + warpN] = mx;
            }
        }
        __syncthreads();

        // combine running stats; rescale O
        float scl[2][2];
        #pragma unroll
        for (int i = 0; i < 2; i++) {
            #pragma unroll
            for (int h2 = 0; h2 < 2; h2++) {
                int rowl = warpM * 32 + i * 16 + gid + 8 * h2;
                float tm = fmaxf(fmaxf(RM[rowl * 4 + 0], RM[rowl * 4 + 1]),
                                 fmaxf(RM[rowl * 4 + 2], RM[rowl * 4 + 3]));
                float mn = fmaxf(m_run[i][h2], tm);
                scl[i][h2] = __expf(m_run[i][h2] - mn);
                m_run[i][h2] = mn;
                l_run[i][h2] *= scl[i][h2];
            }
        }
        #pragma unroll
        for (int i = 0; i < 2; i++)
            #pragma unroll
            for (int j = 0; j < 2; j++) {
                acc_o[i][j][0] *= scl[i][0];
                acc_o[i][j][1] *= scl[i][0];
                acc_o[i][j][2] *= scl[i][1];
                acc_o[i][j][3] *= scl[i][1];
            }

        // p = exp(s - m); partial sums; swizzled STS.64 pair-stores into PA
        float tsum[2][2];
        #pragma unroll
        for (int i = 0; i < 2; i++) { tsum[i][0] = 0.f; tsum[i][1] = 0.f; }

        #pragma unroll
        for (int i = 0; i < 2; i++) {
            #pragma unroll
            for (int j = 0; j < 4; j++) {
                float p0 = __expf(accs[i][j][0] - m_run[i][0]);
                float p1 = __expf(accs[i][j][1] - m_run[i][0]);
                float p2 = __expf(accs[i][j][2] - m_run[i][1]);
                float p3 = __expf(accs[i][j][3] - m_run[i][1]);
                tsum[i][0] += p0 + p1;
                tsum[i][1] += p2 + p3;
                int base = warpN * 2064 + j * 516 + (warpM * 2 + i) * 128;
                *reinterpret_cast<uint2*>(&PA[base + prel0]) = make_uint2(f2tf32(p0), f2tf32(p2));
                *reinterpret_cast<uint2*>(&PA[base + prel1]) = make_uint2(f2tf32(p1), f2tf32(p3));
            }
        }
        #pragma unroll
        for (int i = 0; i < 2; i++) {
            #pragma unroll
            for (int h2 = 0; h2 < 2; h2++) {
                float sv = tsum[i][h2];
                sv += __shfl_xor_sync(0xffffffffu, sv, 1);
                sv += __shfl_xor_sync(0xffffffffu, sv, 2);
                if (tig == 0)
                    RS[(warpM * 32 + i * 16 + gid + 8 * h2) * 4 + warpN] = sv;
            }
        }

        // stage V tile into KVB
        #pragma unroll
        for (int ktv = 0; ktv < 4; ktv++) {
            #pragma unroll
            for (int lp = 0; lp < 2; lp++) {
                int r = rbase + (lp << 5);
                float4 f = *reinterpret_cast<const float4*>(
                    vptr + (size_t)r * SEQ + kbase + ktv * 32 + chunk * 4);
                float bv[4] = {f.x, f.y, f.z, f.w};
                #pragma unroll
                for (int c = 0; c < 4; c++)
                    KVB[ktv * 2128 + bIdx64[lp] + 4 * c] = f2tf32(bv[c]);
            }
        }
        __syncthreads();

        // l update
        #pragma unroll
        for (int i = 0; i < 2; i++) {
            #pragma unroll
            for (int h2 = 0; h2 < 2; h2++) {
                int rowl = warpM * 32 + i * 16 + gid + 8 * h2;
                l_run[i][h2] += RS[rowl * 4 + 0] + RS[rowl * 4 + 1]
                              + RS[rowl * 4 + 2] + RS[rowl * 4 + 3];
            }
        }

        // O += P V   (PA reads use swizzled offset prd)
        #pragma unroll
        for (int ktv = 0; ktv < 4; ktv++) {
            uint4 bf[2][2];
            #pragma unroll
            for (int kp = 0; kp < 2; kp++)
                #pragma unroll
                for (int j = 0; j < 2; j++)
                    bf[kp][j] = *reinterpret_cast<const uint4*>(
                        &KVB[ktv * 2128 + kp * 1064 + (warpN * 2 + j) * 132 + lane * 4]);
            #pragma unroll
            for (int ks = 0; ks < 4; ks++) {
                uint4 af[2];
                #pragma unroll
                for (int i = 0; i < 2; i++)
                    af[i] = *reinterpret_cast<const uint4*>(
                        &PA[ktv * 2064 + ks * 516 + (warpM * 2 + i) * 128 + prd]);
                const int kp = ks >> 1, odd = ks & 1;
                #pragma unroll
                for (int i = 0; i < 2; i++)
                    #pragma unroll
                    for (int j = 0; j < 2; j++) {
                        uint32_t b0 = odd ? bf[kp][j].z : bf[kp][j].x;
                        uint32_t b1 = odd ? bf[kp][j].w : bf[kp][j].y;
                        mma8(acc_o[i][j], af[i], b0, b1);
                    }
            }
        }
        __syncthreads();
    }

    // epilogue: O / l
    #pragma unroll
    for (int i = 0; i < 2; i++) {
        int row0 = bm + warpM * 32 + i * 16 + gid;
        float inv0 = 1.0f / l_run[i][0];
        float inv1 = 1.0f / l_run[i][1];
        #pragma unroll
        for (int j = 0; j < 2; j++) {
            int col = warpN * 16 + j * 8 + tig * 2;
            *reinterpret_cast<float2*>(o + ((size_t)(b * SEQ + row0)) * EMB + h * HD + col) =
                make_float2(acc_o[i][j][0] * inv0, acc_o[i][j][1] * inv0);
            *reinterpret_cast<float2*>(o + ((size_t)(b * SEQ + row0 + 8)) * EMB + h * HD + col) =
                make_float2(acc_o[i][j][2] * inv1, acc_o[i][j][3] * inv1);
        }
    }
}

// ---------------- launch ----------------
extern "C" void kernel_launch(void* const* d_in, const int* in_sizes, int n_in,
                              void* d_out, int out_size)
{
    const float* x   = (const float*)d_in[0];
    const int*   mask= (const int*)  d_in[1];
    const float* Wq  = (const float*)d_in[2];
    const float* bq  = (const float*)d_in[3];
    const float* Wk  = (const float*)d_in[4];
    const float* bk  = (const float*)d_in[5];
    const float* Wv  = (const float*)d_in[6];
    const float* bv  = (const float*)d_in[7];
    const float* Wo  = (const float*)d_in[8];
    const float* bo  = (const float*)d_in[9];
    const float* W1  = (const float*)d_in[10];
    const float* b1  = (const float*)d_in[11];
    const float* W2  = (const float*)d_in[12];
    const float* b2  = (const float*)d_in[13];
    const float* g1  = (const float*)d_in[14];
    const float* be1 = (const float*)d_in[15];
    const float* g2  = (const float*)d_in[16];
    const float* be2 = (const float*)d_in[17];
    float* out = (float*)d_out;

    float *nx, *q, *k, *v, *vt, *o, *x1, *nx2, *hbuf;
    cudaGetSymbolAddress((void**)&nx,   g_nx);
    cudaGetSymbolAddress((void**)&q,    g_q);
    cudaGetSymbolAddress((void**)&k,    g_k);
    cudaGetSymbolAddress((void**)&v,    g_v);
    cudaGetSymbolAddress((void**)&vt,   g_vt);
    cudaGetSymbolAddress((void**)&o,    g_o);
    cudaGetSymbolAddress((void**)&x1,   g_x1);
    cudaGetSymbolAddress((void**)&nx2,  g_nx2);
    cudaGetSymbolAddress((void**)&hbuf, g_h);

    cudaFuncSetAttribute(flash_attn, cudaFuncAttributeMaxDynamicSharedMemorySize, FA_SMEM_BYTES);

    const dim3 gEE(EMB / 128, MROWS / 128);
    const dim3 gFF(DFF / 128, MROWS / 128);

    layernorm_k<<<MROWS, 256>>>(x, g1, be1, nx);
    gemm_qkv<<<dim3(EMB / 128, MROWS / 128, 3), 256>>>(nx, Wq, Wk, Wv, bq, bk, bv, q, k, v);

    transpose_v_k<<<dim3(SEQ / 32, HD / 32, BB * NH), 256>>>(v, vt);
    flash_attn<<<dim3(SEQ / 64, BB * NH), 256, FA_SMEM_BYTES>>>(q, k, vt, mask, o);

    gemm_tc<0><<<gEE, 256>>>(o, Wo, bo, x, x1, MROWS, EMB, EMB);
    layernorm_k<<<MROWS, 256>>>(x1, g2, be2, nx2);
    gemm_tc<1><<<gFF, 256>>>(nx2, W1, b1, nullptr, hbuf, MROWS, DFF, EMB);
    gemm_tc<0><<<gEE, 256>>>(hbuf, W2, b2, x1, out, MROWS, EMB, DFF);
}